// round 2
// baseline (speedup 1.0000x reference)
#include <cuda_runtime.h>
#include <math.h>

#define N_NODES 2048
#define N_EDGES 49152
#define HID     80
#define AGGD    96
#define WN      3328

__device__ float g_geo[N_EDGES * 20];
__device__ float g_f2 [N_EDGES * 64];
__device__ float g_h    [N_NODES * HID];
__device__ float g_hx   [N_NODES * HID];
__device__ float g_xself[N_NODES * HID];
__device__ float g_agg  [N_NODES * AGGD];

__global__ void k_geo(const float* __restrict__ pos, const int* __restrict__ ei) {
    int e = blockIdx.x * blockDim.x + threadIdx.x;
    if (e >= N_EDGES) return;
    int s = ei[e], d = ei[N_EDGES + e];
    float rx = pos[d*3+0]-pos[s*3+0], ry = pos[d*3+1]-pos[s*3+1], rz = pos[d*3+2]-pos[s*3+2];
    float r = fmaxf(sqrtf(rx*rx+ry*ry+rz*rz), 1e-6f);
    float inv = 1.f/r;
    float dx = rx*inv, dy = ry*inv, dz = rz*inv;
    float* g = g_geo + e*20;
    const float s3 = 1.7320508075688772f;
    g[0]=s3*dx; g[1]=s3*dy; g[2]=s3*dz;
    const float c15 = 3.872983346207417f;
    float y20=c15*dx*dy, y21=c15*dy*dz, y22=1.1180339887498949f*(3.f*dz*dz-1.f);
    float y23=c15*dx*dz, y24=0.5f*c15*(dx*dx-dy*dy);
    const float s2=0.7071067811865476f, s6=0.4082482904638631f, q=0.7745966692414834f;
    g[3]=q*(-s6*y22+s2*y24); g[4]=q*(-s6*y22-s2*y24); g[5]=q*(2.f*s6*y22);
    g[6]=q*s2*y20; g[7]=q*s2*y21; g[8]=q*s2*y23;
    float u = r*(1.f/6.f);
    float u3=u*u*u, u6=u3*u3, u7=u6*u, u8=u7*u;
    float fc = (u<1.f) ? (1.f-28.f*u6+48.f*u7-21.f*u8) : 0.f;
    float pref = 0.5773502691896258f*inv*fc; // sqrt(2/6)
    float pir = 3.14159265358979323846f*r*(1.f/6.f);
    #pragma unroll
    for (int n = 1; n <= 8; ++n) g[8+n] = pref*sinf((float)n*pir);
}

__global__ void k_init(const float* __restrict__ x, const float* __restrict__ ew) {
    int idx = blockIdx.x*blockDim.x + threadIdx.x;
    if (idx >= N_NODES*HID) return;
    int n = idx/HID, c = idx - n*HID;
    float v = 0.f;
    if (c < 32) {
        float a = 0.f;
        #pragma unroll
        for (int u = 0; u < 16; ++u) a = fmaf(x[n*16+u], ew[u*32+c], a);
        v = a*0.25f;
    }
    g_h[idx] = v;
}

__global__ void k_nodelin(const float* __restrict__ Ws, const float* __restrict__ Wv,
                          const float* __restrict__ Ss, const float* __restrict__ Sv) {
    __shared__ float ws_[1024], wv_[256], ss_[1024], sv_[256];
    int tid = threadIdx.x;
    for (int i = tid; i < 1024; i += 256) { ws_[i]=Ws[i]; ss_[i]=Ss[i]; }
    if (tid < 256) { wv_[tid]=Wv[tid]; sv_[tid]=Sv[tid]; }
    __syncthreads();
    int n = blockIdx.x*256 + tid;
    float hs[32], hv[48];
    #pragma unroll
    for (int i = 0; i < 32; ++i) hs[i] = g_h[n*HID+i];
    #pragma unroll
    for (int i = 0; i < 48; ++i) hv[i] = g_h[n*HID+32+i];
    const float is = 0.17677669529663687f, iv = 0.25f;
    for (int w = 0; w < 32; ++w) {
        float a=0.f, b=0.f;
        #pragma unroll
        for (int u = 0; u < 32; ++u) { a=fmaf(hs[u],ws_[u*32+w],a); b=fmaf(hs[u],ss_[u*32+w],b); }
        g_hx[n*HID+w]=a*is; g_xself[n*HID+w]=b*is;
    }
    for (int w = 0; w < 16; ++w) {
        float a0=0,a1=0,a2=0,b0=0,b1=0,b2=0;
        #pragma unroll
        for (int u = 0; u < 16; ++u) {
            float wl=wv_[u*16+w], sl=sv_[u*16+w];
            a0=fmaf(hv[u*3+0],wl,a0); a1=fmaf(hv[u*3+1],wl,a1); a2=fmaf(hv[u*3+2],wl,a2);
            b0=fmaf(hv[u*3+0],sl,b0); b1=fmaf(hv[u*3+1],sl,b1); b2=fmaf(hv[u*3+2],sl,b2);
        }
        g_hx[n*HID+32+w*3+0]=a0*iv; g_hx[n*HID+32+w*3+1]=a1*iv; g_hx[n*HID+32+w*3+2]=a2*iv;
        g_xself[n*HID+32+w*3+0]=b0*iv; g_xself[n*HID+32+w*3+1]=b1*iv; g_xself[n*HID+32+w*3+2]=b2*iv;
    }
}

__global__ void k_radial(const float* __restrict__ W1, const float* __restrict__ B1,
                         const float* __restrict__ W2, const float* __restrict__ B2) {
    __shared__ float w1s[512], b1s[64], w2s[4096], b2s[64];
    int tid = threadIdx.x;
    for (int i = tid; i < 512;  i += 256) w1s[i]=W1[i];
    for (int i = tid; i < 4096; i += 256) w2s[i]=W2[i];
    if (tid < 64) { b1s[tid]=B1[tid]; b2s[tid]=B2[tid]; }
    __syncthreads();
    int e = blockIdx.x*256 + tid;
    float rbf[8];
    #pragma unroll
    for (int n = 0; n < 8; ++n) rbf[n] = g_geo[e*20+9+n];
    float f1[64];
    #pragma unroll
    for (int o = 0; o < 64; ++o) {
        float a = b1s[o];
        #pragma unroll
        for (int n = 0; n < 8; ++n) a = fmaf(rbf[n], w1s[n*64+o], a);
        f1[o] = a/(1.f+expf(-a));
    }
    for (int o = 0; o < 64; ++o) {
        float a = b2s[o];
        #pragma unroll
        for (int k = 0; k < 64; ++k) a = fmaf(f1[k], w2s[k*64+o], a);
        g_f2[e*64+o] = a/(1.f+expf(-a));
    }
}

__global__ void k_zero() {
    int i = blockIdx.x*blockDim.x + threadIdx.x;
    if (i < N_NODES*AGGD) g_agg[i] = 0.f;
}

struct SmemK3 {
    float Wc[64*128];
    float b3c[128];
    float sj[32*64];
    float p2[16*64];
    float vj[48*64];
    float q5[48*64];
    float y1[3*64];
    float Mq[6*64];
    float t3[16*64];
    float accs[48*64];
    float accv[48*64];
    int srcs[64];
    int dsts[64];
};

__device__ __forceinline__ void chunk_load(SmemK3* sm, const float* __restrict__ W3,
                                           const float* __restrict__ B3,
                                           int tid, int base, int U, int W, int w0) {
    __syncthreads();
    int logU = (U == 32) ? 5 : 4;
    for (int g = tid; g < 64*U; g += 256) {
        int k = g >> logU, u = g & (U-1);
        float4 v = *(const float4*)(W3 + k*WN + base + u*W + w0);
        sm->Wc[k*128 + 0*U + u] = v.x;
        sm->Wc[k*128 + 1*U + u] = v.y;
        sm->Wc[k*128 + 2*U + u] = v.z;
        sm->Wc[k*128 + 3*U + u] = v.w;
    }
    if (tid < 4*U) {
        int w_ = tid >> logU, u = tid & (U-1);
        sm->b3c[tid] = B3[base + u*W + w0 + w_];
    }
    __syncthreads();
}

template <int U>
__device__ __forceinline__ void dot4(const SmemK3* sm, const float (&fr)[64], int wp, int u0,
                                     float& c0, float& c1, float& c2, float& c3) {
    c0 = sm->b3c[wp*U+u0+0]; c1 = sm->b3c[wp*U+u0+1];
    c2 = sm->b3c[wp*U+u0+2]; c3 = sm->b3c[wp*U+u0+3];
    #pragma unroll
    for (int k = 0; k < 64; ++k) {
        float4 wv = *(const float4*)&sm->Wc[k*128 + wp*U + u0];
        float fk = fr[k];
        c0 = fmaf(fk, wv.x, c0); c1 = fmaf(fk, wv.y, c1);
        c2 = fmaf(fk, wv.z, c2); c3 = fmaf(fk, wv.w, c3);
    }
}

__global__ __launch_bounds__(256)
void k_msg(const int* __restrict__ ei, const float* __restrict__ W3, const float* __restrict__ B3) {
    extern __shared__ unsigned char smraw[];
    SmemK3* sm = (SmemK3*)smraw;
    int tid = threadIdx.x;
    int e = tid & 63, wp = tid >> 6;
    int e0 = blockIdx.x*64;

    if (tid < 64) { sm->srcs[tid] = ei[e0+tid]; sm->dsts[tid] = ei[N_EDGES+e0+tid]; }
    __syncthreads();
    for (int i = tid; i < 64*80; i += 256) {
        int ee = i/80, c = i - ee*80;
        float v = g_hx[sm->srcs[ee]*HID + c];
        if (c < 32) sm->sj[c*64+ee] = v; else sm->vj[(c-32)*64+ee] = v;
    }
    for (int i = tid; i < 64*9; i += 256) {
        int ee = i/9, c = i - ee*9;
        float v = g_geo[(e0+ee)*20 + c];
        if (c < 3) sm->y1[c*64+ee] = v; else sm->Mq[(c-3)*64+ee] = v;
    }
    { float* z = sm->t3; for (int i = tid; i < 7168; i += 256) z[i] = 0.f; }
    __syncthreads();
    for (int i = tid; i < 64*16; i += 256) {
        int ee = i & 63, u = i >> 6;
        float v0 = sm->vj[(u*3+0)*64+ee], v1 = sm->vj[(u*3+1)*64+ee], v2 = sm->vj[(u*3+2)*64+ee];
        float y0 = sm->y1[0*64+ee], yy = sm->y1[64+ee], yz = sm->y1[128+ee];
        sm->p2[u*64+ee] = (v0*y0+v1*yy+v2*yz)*0.5773502691896258f;
        float M00=sm->Mq[0*64+ee],M11=sm->Mq[64+ee],M22=sm->Mq[128+ee];
        float M01=sm->Mq[192+ee],M12=sm->Mq[256+ee],M02=sm->Mq[320+ee];
        sm->q5[(u*3+0)*64+ee]=v0*M00+v1*M01+v2*M02;
        sm->q5[(u*3+1)*64+ee]=v0*M01+v1*M11+v2*M12;
        sm->q5[(u*3+2)*64+ee]=v0*M02+v1*M12+v2*M22;
    }
    float fr[64];
    {
        const float4* fp = (const float4*)&g_f2[(e0+e)*64];
        #pragma unroll
        for (int q = 0; q < 16; ++q) {
            float4 v = fp[q];
            fr[q*4+0]=v.x; fr[q*4+1]=v.y; fr[q*4+2]=v.z; fr[q*4+3]=v.w;
        }
    }
    __syncthreads();

    for (int w0 = 0; w0 < 48; w0 += 4) {               // bucket 1: U=32, sj -> accs
        chunk_load(sm, W3, B3, tid, 0, 32, 48, w0);
        float a = 0.f;
        for (int u0 = 0; u0 < 32; u0 += 4) {
            float c0,c1,c2,c3; dot4<32>(sm, fr, wp, u0, c0,c1,c2,c3);
            a = fmaf(sm->sj[(u0+0)*64+e],c0,a); a = fmaf(sm->sj[(u0+1)*64+e],c1,a);
            a = fmaf(sm->sj[(u0+2)*64+e],c2,a); a = fmaf(sm->sj[(u0+3)*64+e],c3,a);
        }
        sm->accs[(w0+wp)*64+e] += a;
    }
    for (int w0 = 0; w0 < 48; w0 += 4) {               // bucket 2: U=16, p2 -> accs
        chunk_load(sm, W3, B3, tid, 1536, 16, 48, w0);
        float a = 0.f;
        for (int u0 = 0; u0 < 16; u0 += 4) {
            float c0,c1,c2,c3; dot4<16>(sm, fr, wp, u0, c0,c1,c2,c3);
            a = fmaf(sm->p2[(u0+0)*64+e],c0,a); a = fmaf(sm->p2[(u0+1)*64+e],c1,a);
            a = fmaf(sm->p2[(u0+2)*64+e],c2,a); a = fmaf(sm->p2[(u0+3)*64+e],c3,a);
        }
        sm->accs[(w0+wp)*64+e] += a;
    }
    for (int w0 = 0; w0 < 16; w0 += 4) {               // bucket 3: U=32, sj -> t3
        chunk_load(sm, W3, B3, tid, 2304, 32, 16, w0);
        float a = 0.f;
        for (int u0 = 0; u0 < 32; u0 += 4) {
            float c0,c1,c2,c3; dot4<32>(sm, fr, wp, u0, c0,c1,c2,c3);
            a = fmaf(sm->sj[(u0+0)*64+e],c0,a); a = fmaf(sm->sj[(u0+1)*64+e],c1,a);
            a = fmaf(sm->sj[(u0+2)*64+e],c2,a); a = fmaf(sm->sj[(u0+3)*64+e],c3,a);
        }
        sm->t3[(w0+wp)*64+e] += a;
    }
    for (int w0 = 0; w0 < 16; w0 += 4) {               // bucket 4: U=16, vj -> accv
        chunk_load(sm, W3, B3, tid, 2816, 16, 16, w0);
        float a0=0,a1=0,a2=0;
        for (int u0 = 0; u0 < 16; u0 += 4) {
            float cs[4]; dot4<16>(sm, fr, wp, u0, cs[0],cs[1],cs[2],cs[3]);
            #pragma unroll
            for (int j = 0; j < 4; ++j) {
                int u = u0+j;
                a0 = fmaf(sm->vj[(u*3+0)*64+e],cs[j],a0);
                a1 = fmaf(sm->vj[(u*3+1)*64+e],cs[j],a1);
                a2 = fmaf(sm->vj[(u*3+2)*64+e],cs[j],a2);
            }
        }
        sm->accv[((w0+wp)*3+0)*64+e] += a0;
        sm->accv[((w0+wp)*3+1)*64+e] += a1;
        sm->accv[((w0+wp)*3+2)*64+e] += a2;
    }
    for (int w0 = 0; w0 < 16; w0 += 4) {               // bucket 5: U=16, q5 -> accv
        chunk_load(sm, W3, B3, tid, 3072, 16, 16, w0);
        float a0=0,a1=0,a2=0;
        for (int u0 = 0; u0 < 16; u0 += 4) {
            float cs[4]; dot4<16>(sm, fr, wp, u0, cs[0],cs[1],cs[2],cs[3]);
            #pragma unroll
            for (int j = 0; j < 4; ++j) {
                int u = u0+j;
                a0 = fmaf(sm->q5[(u*3+0)*64+e],cs[j],a0);
                a1 = fmaf(sm->q5[(u*3+1)*64+e],cs[j],a1);
                a2 = fmaf(sm->q5[(u*3+2)*64+e],cs[j],a2);
            }
        }
        sm->accv[((w0+wp)*3+0)*64+e] += a0;
        sm->accv[((w0+wp)*3+1)*64+e] += a1;
        sm->accv[((w0+wp)*3+2)*64+e] += a2;
    }
    __syncthreads();

    const float SS = 0.029462782549439483f;  // 1/sqrt(48*24)
    const float SV = 0.025515518153991442f;  // 1/sqrt(64*24)
    int dd = sm->dsts[e];
    for (int c = wp*24; c < wp*24+24; ++c) {
        float val;
        if (c < 48) val = sm->accs[c*64+e]*SS;
        else {
            int cc = c-48, w = cc/3, i = cc-w*3;
            val = (sm->accv[cc*64+e] + sm->y1[i*64+e]*sm->t3[w*64+e])*SV;
        }
        atomicAdd(&g_agg[dd*AGGD+c], val);
    }
}

__global__ void k_gate() {
    int idx = blockIdx.x*blockDim.x + threadIdx.x;
    if (idx >= N_NODES*HID) return;
    int n = idx/HID, c = idx - n*HID;
    float add;
    if (c < 32) {
        float a = g_agg[n*AGGD+c];
        add = a/(1.f+expf(-a));
    } else {
        int cc = c-32, w = cc/3;
        float gg = g_agg[n*AGGD+32+w];
        add = g_agg[n*AGGD+48+cc]/(1.f+expf(-gg));
    }
    g_h[idx] = g_h[idx] + g_xself[idx] + add;
}

__global__ void k_out(const float* __restrict__ proj, float* __restrict__ out) {
    int idx = blockIdx.x*blockDim.x + threadIdx.x;
    if (idx >= N_NODES*32) return;
    int n = idx >> 5, j = idx & 31;
    float a = 0.f;
    #pragma unroll
    for (int u = 0; u < 32; ++u) a = fmaf(g_h[n*HID+u], proj[u*32+j], a);
    out[idx] = a*0.17677669529663687f;
}

extern "C" void kernel_launch(void* const* d_in, const int* in_sizes, int n_in,
                              void* d_out, int out_size) {
    const float* x      = (const float*)d_in[0];
    const float* pos    = (const float*)d_in[1];
    const int*   ei     = (const int*)  d_in[2];
    const float* embed  = (const float*)d_in[3];
    const float* proj   = (const float*)d_in[4];
    const float* lin_ws = (const float*)d_in[5];
    const float* lin_wv = (const float*)d_in[6];
    const float* sc_ws  = (const float*)d_in[7];
    const float* sc_wv  = (const float*)d_in[8];
    const float* w1     = (const float*)d_in[9];
    const float* b1     = (const float*)d_in[10];
    const float* w2     = (const float*)d_in[11];
    const float* b2     = (const float*)d_in[12];
    const float* w3     = (const float*)d_in[13];
    const float* b3     = (const float*)d_in[14];

    cudaFuncSetAttribute(k_msg, cudaFuncAttributeMaxDynamicSharedMemorySize, (int)sizeof(SmemK3));

    k_geo<<<192, 256>>>(pos, ei);
    k_init<<<640, 256>>>(x, embed);
    for (int l = 0; l < 4; ++l) {
        k_nodelin<<<8, 256>>>(lin_ws + l*1024, lin_wv + l*256, sc_ws + l*1024, sc_wv + l*256);
        k_radial<<<192, 256>>>(w1 + l*512, b1 + l*64, w2 + l*4096, b2 + l*64);
        k_zero<<<768, 256>>>();
        k_msg<<<768, 256, sizeof(SmemK3)>>>(ei, w3 + l*64*WN, b3 + l*WN);
        k_gate<<<640, 256>>>();
    }
    k_out<<<256, 256>>>(proj, (float*)d_out);
}

// round 5
// speedup vs baseline: 1.0432x; 1.0432x over previous
#include <cuda_runtime.h>
#include <math.h>

#define N_NODES 2048
#define N_EDGES 49152
#define HID     80
#define AGGD    96
#define WN      3328

__device__ float g_geo[N_EDGES * 20];
__device__ float g_f2 [N_EDGES * 64];
__device__ float g_h    [N_NODES * HID];
__device__ float g_hx   [N_NODES * HID];
__device__ float g_xself[N_NODES * HID];
__device__ float g_agg  [N_NODES * AGGD];

typedef unsigned long long u64;

__device__ __forceinline__ u64 fma2(u64 a, u64 b, u64 c) {
    u64 d;
    asm("fma.rn.f32x2 %0, %1, %2, %3;" : "=l"(d) : "l"(a), "l"(b), "l"(c));
    return d;
}
__device__ __forceinline__ float lo2(u64 v){ return __uint_as_float((unsigned)v); }
__device__ __forceinline__ float hi2(u64 v){ return __uint_as_float((unsigned)(v>>32)); }

__global__ void k_geo(const float* __restrict__ pos, const int* __restrict__ ei) {
    int e = blockIdx.x * blockDim.x + threadIdx.x;
    if (e >= N_EDGES) return;
    int s = ei[e], d = ei[N_EDGES + e];
    float rx = pos[d*3+0]-pos[s*3+0], ry = pos[d*3+1]-pos[s*3+1], rz = pos[d*3+2]-pos[s*3+2];
    float r = fmaxf(sqrtf(rx*rx+ry*ry+rz*rz), 1e-6f);
    float inv = 1.f/r;
    float dx = rx*inv, dy = ry*inv, dz = rz*inv;
    float* g = g_geo + e*20;
    const float s3 = 1.7320508075688772f;
    g[0]=s3*dx; g[1]=s3*dy; g[2]=s3*dz;
    const float c15 = 3.872983346207417f;
    float y20=c15*dx*dy, y21=c15*dy*dz, y22=1.1180339887498949f*(3.f*dz*dz-1.f);
    float y23=c15*dx*dz, y24=0.5f*c15*(dx*dx-dy*dy);
    const float s2=0.7071067811865476f, s6=0.4082482904638631f, q=0.7745966692414834f;
    g[3]=q*(-s6*y22+s2*y24); g[4]=q*(-s6*y22-s2*y24); g[5]=q*(2.f*s6*y22);
    g[6]=q*s2*y20; g[7]=q*s2*y21; g[8]=q*s2*y23;
    float u = r*(1.f/6.f);
    float u3=u*u*u, u6=u3*u3, u7=u6*u, u8=u7*u;
    float fc = (u<1.f) ? (1.f-28.f*u6+48.f*u7-21.f*u8) : 0.f;
    float pref = 0.5773502691896258f*inv*fc;
    float pir = 3.14159265358979323846f*r*(1.f/6.f);
    #pragma unroll
    for (int n = 1; n <= 8; ++n) g[8+n] = pref*sinf((float)n*pir);
}

__global__ void k_init(const float* __restrict__ x, const float* __restrict__ ew) {
    int idx = blockIdx.x*blockDim.x + threadIdx.x;
    if (idx >= N_NODES*HID) return;
    int n = idx/HID, c = idx - n*HID;
    float v = 0.f;
    if (c < 32) {
        float a = 0.f;
        #pragma unroll
        for (int u = 0; u < 16; ++u) a = fmaf(x[n*16+u], ew[u*32+c], a);
        v = a*0.25f;
    }
    g_h[idx] = v;
}

__global__ void k_nodelin(const float* __restrict__ Ws, const float* __restrict__ Wv,
                          const float* __restrict__ Ss, const float* __restrict__ Sv) {
    __shared__ float ws_[1024], wv_[256], ss_[1024], sv_[256];
    int tid = threadIdx.x;
    for (int i = tid; i < 1024; i += 256) { ws_[i]=Ws[i]; ss_[i]=Ss[i]; }
    if (tid < 256) { wv_[tid]=Wv[tid]; sv_[tid]=Sv[tid]; }
    __syncthreads();
    int n = blockIdx.x*256 + tid;
    float hs[32], hv[48];
    #pragma unroll
    for (int i = 0; i < 32; ++i) hs[i] = g_h[n*HID+i];
    #pragma unroll
    for (int i = 0; i < 48; ++i) hv[i] = g_h[n*HID+32+i];
    const float is = 0.17677669529663687f, iv = 0.25f;
    for (int w = 0; w < 32; ++w) {
        float a=0.f, b=0.f;
        #pragma unroll
        for (int u = 0; u < 32; ++u) { a=fmaf(hs[u],ws_[u*32+w],a); b=fmaf(hs[u],ss_[u*32+w],b); }
        g_hx[n*HID+w]=a*is; g_xself[n*HID+w]=b*is;
    }
    for (int w = 0; w < 16; ++w) {
        float a0=0,a1=0,a2=0,b0=0,b1=0,b2=0;
        #pragma unroll
        for (int u = 0; u < 16; ++u) {
            float wl=wv_[u*16+w], sl=sv_[u*16+w];
            a0=fmaf(hv[u*3+0],wl,a0); a1=fmaf(hv[u*3+1],wl,a1); a2=fmaf(hv[u*3+2],wl,a2);
            b0=fmaf(hv[u*3+0],sl,b0); b1=fmaf(hv[u*3+1],sl,b1); b2=fmaf(hv[u*3+2],sl,b2);
        }
        g_hx[n*HID+32+w*3+0]=a0*iv; g_hx[n*HID+32+w*3+1]=a1*iv; g_hx[n*HID+32+w*3+2]=a2*iv;
        g_xself[n*HID+32+w*3+0]=b0*iv; g_xself[n*HID+32+w*3+1]=b1*iv; g_xself[n*HID+32+w*3+2]=b2*iv;
    }
}

// 4 threads per edge: each computes full f1 in registers, then 16 of 64 outputs.
__global__ __launch_bounds__(256)
void k_radial(const float* __restrict__ W1, const float* __restrict__ B1,
              const float* __restrict__ W2, const float* __restrict__ B2) {
    __shared__ float w1s[512], b1s[64], w2s[4096], b2s[64];
    int tid = threadIdx.x;
    for (int i = tid; i < 512;  i += 256) w1s[i]=W1[i];
    for (int i = tid; i < 4096; i += 256) w2s[i]=W2[i];
    if (tid < 64) { b1s[tid]=B1[tid]; b2s[tid]=B2[tid]; }
    __syncthreads();
    int e = blockIdx.x*64 + (tid>>2);
    int part = (tid&3)*16;
    float rbf[8];
    #pragma unroll
    for (int n = 0; n < 8; ++n) rbf[n] = g_geo[e*20+9+n];
    float f1[64];
    #pragma unroll
    for (int o = 0; o < 64; ++o) {
        float a = b1s[o];
        #pragma unroll
        for (int n = 0; n < 8; ++n) a = fmaf(rbf[n], w1s[n*64+o], a);
        f1[o] = a/(1.f+__expf(-a));
    }
    #pragma unroll
    for (int oo = 0; oo < 16; ++oo) {
        int o = part + oo;
        float a = b2s[o];
        #pragma unroll
        for (int k = 0; k < 64; ++k) a = fmaf(f1[k], w2s[k*64+o], a);
        g_f2[e*64+o] = a/(1.f+__expf(-a));
    }
}

__global__ void k_zero() {
    int i = blockIdx.x*blockDim.x + threadIdx.x;
    if (i < N_NODES*AGGD) g_agg[i] = 0.f;
}

struct SmemK3 {
    float Wc[64*128];   // [k2][w'(4)][u(U)][kpar(2)]
    float b3c[128];
    float sj[32*64];
    float p2[16*64];
    float vj[48*64];
    float q5[48*64];
    float y1[3*64];
    float Mq[6*64];
    float t3[16*64];
    float accs[48*64];
    float accv[48*64];
    int srcs[64];
    int dsts[64];
};

__device__ __forceinline__ void chunk_load(SmemK3* sm, const float* __restrict__ W3,
                                           const float* __restrict__ B3,
                                           int tid, int base, int U, int W, int w0) {
    __syncthreads();
    int logU = (U == 32) ? 5 : 4;
    for (int g = tid; g < 64*U; g += 256) {
        int k = g >> logU, u = g & (U-1);
        float4 v = *(const float4*)(W3 + k*WN + base + u*W + w0);
        float* dst = sm->Wc + (k>>1)*(8*U) + (k&1);
        dst[(0*U+u)*2] = v.x;
        dst[(1*U+u)*2] = v.y;
        dst[(2*U+u)*2] = v.z;
        dst[(3*U+u)*2] = v.w;
    }
    if (tid < 4*U) {
        int w_ = tid >> logU, u = tid & (U-1);
        sm->b3c[tid] = B3[base + u*W + w0 + w_];
    }
    __syncthreads();
}

template <int U>
__device__ __forceinline__ void dot4(const SmemK3* sm, const u64 (&frp)[32], int wp, int u0,
                                     float& c0, float& c1, float& c2, float& c3) {
    u64 a0=0ULL, a1=0ULL, a2=0ULL, a3=0ULL;
    const float* basep = sm->Wc + (wp*U + u0)*2;
    #pragma unroll
    for (int k2 = 0; k2 < 32; ++k2) {
        const float* p = basep + k2*(8*U);
        ulonglong2 w01 = *(const ulonglong2*)p;
        ulonglong2 w23 = *(const ulonglong2*)(p+4);
        u64 f = frp[k2];
        a0 = fma2(f, w01.x, a0);
        a1 = fma2(f, w01.y, a1);
        a2 = fma2(f, w23.x, a2);
        a3 = fma2(f, w23.y, a3);
    }
    c0 = sm->b3c[wp*U+u0+0] + lo2(a0) + hi2(a0);
    c1 = sm->b3c[wp*U+u0+1] + lo2(a1) + hi2(a1);
    c2 = sm->b3c[wp*U+u0+2] + lo2(a2) + hi2(a2);
    c3 = sm->b3c[wp*U+u0+3] + lo2(a3) + hi2(a3);
}

__global__ __launch_bounds__(256)
void k_msg(const int* __restrict__ ei, const float* __restrict__ W3, const float* __restrict__ B3) {
    extern __shared__ unsigned char smraw[];
    SmemK3* sm = (SmemK3*)smraw;
    int tid = threadIdx.x;
    int e = tid & 63, wp = tid >> 6;
    int e0 = blockIdx.x*64;

    if (tid < 64) { sm->srcs[tid] = ei[e0+tid]; sm->dsts[tid] = ei[N_EDGES+e0+tid]; }
    __syncthreads();
    for (int i = tid; i < 64*80; i += 256) {
        int ee = i/80, c = i - ee*80;
        float v = g_hx[sm->srcs[ee]*HID + c];
        if (c < 32) sm->sj[c*64+ee] = v; else sm->vj[(c-32)*64+ee] = v;
    }
    for (int i = tid; i < 64*9; i += 256) {
        int ee = i/9, c = i - ee*9;
        float v = g_geo[(e0+ee)*20 + c];
        if (c < 3) sm->y1[c*64+ee] = v; else sm->Mq[(c-3)*64+ee] = v;
    }
    { float* z = sm->t3; for (int i = tid; i < 7168; i += 256) z[i] = 0.f; }
    __syncthreads();
    for (int i = tid; i < 64*16; i += 256) {
        int ee = i & 63, u = i >> 6;
        float v0 = sm->vj[(u*3+0)*64+ee], v1 = sm->vj[(u*3+1)*64+ee], v2 = sm->vj[(u*3+2)*64+ee];
        float y0 = sm->y1[0*64+ee], yy = sm->y1[64+ee], yz = sm->y1[128+ee];
        sm->p2[u*64+ee] = (v0*y0+v1*yy+v2*yz)*0.5773502691896258f;
        float M00=sm->Mq[0*64+ee],M11=sm->Mq[64+ee],M22=sm->Mq[128+ee];
        float M01=sm->Mq[192+ee],M12=sm->Mq[256+ee],M02=sm->Mq[320+ee];
        sm->q5[(u*3+0)*64+ee]=v0*M00+v1*M01+v2*M02;
        sm->q5[(u*3+1)*64+ee]=v0*M01+v1*M11+v2*M12;
        sm->q5[(u*3+2)*64+ee]=v0*M02+v1*M12+v2*M22;
    }
    u64 frp[32];
    {
        const ulonglong2* fp = (const ulonglong2*)&g_f2[(e0+e)*64];
        #pragma unroll
        for (int q = 0; q < 16; ++q) {
            ulonglong2 v = fp[q];
            frp[2*q] = v.x; frp[2*q+1] = v.y;
        }
    }
    __syncthreads();

    for (int w0 = 0; w0 < 48; w0 += 4) {               // bucket 1: U=32, sj -> accs
        chunk_load(sm, W3, B3, tid, 0, 32, 48, w0);
        float a = 0.f;
        for (int u0 = 0; u0 < 32; u0 += 4) {
            float c0,c1,c2,c3; dot4<32>(sm, frp, wp, u0, c0,c1,c2,c3);
            a = fmaf(sm->sj[(u0+0)*64+e],c0,a); a = fmaf(sm->sj[(u0+1)*64+e],c1,a);
            a = fmaf(sm->sj[(u0+2)*64+e],c2,a); a = fmaf(sm->sj[(u0+3)*64+e],c3,a);
        }
        sm->accs[(w0+wp)*64+e] += a;
    }
    for (int w0 = 0; w0 < 48; w0 += 4) {               // bucket 2: U=16, p2 -> accs
        chunk_load(sm, W3, B3, tid, 1536, 16, 48, w0);
        float a = 0.f;
        for (int u0 = 0; u0 < 16; u0 += 4) {
            float c0,c1,c2,c3; dot4<16>(sm, frp, wp, u0, c0,c1,c2,c3);
            a = fmaf(sm->p2[(u0+0)*64+e],c0,a); a = fmaf(sm->p2[(u0+1)*64+e],c1,a);
            a = fmaf(sm->p2[(u0+2)*64+e],c2,a); a = fmaf(sm->p2[(u0+3)*64+e],c3,a);
        }
        sm->accs[(w0+wp)*64+e] += a;
    }
    for (int w0 = 0; w0 < 16; w0 += 4) {               // bucket 3: U=32, sj -> t3
        chunk_load(sm, W3, B3, tid, 2304, 32, 16, w0);
        float a = 0.f;
        for (int u0 = 0; u0 < 32; u0 += 4) {
            float c0,c1,c2,c3; dot4<32>(sm, frp, wp, u0, c0,c1,c2,c3);
            a = fmaf(sm->sj[(u0+0)*64+e],c0,a); a = fmaf(sm->sj[(u0+1)*64+e],c1,a);
            a = fmaf(sm->sj[(u0+2)*64+e],c2,a); a = fmaf(sm->sj[(u0+3)*64+e],c3,a);
        }
        sm->t3[(w0+wp)*64+e] += a;
    }
    for (int w0 = 0; w0 < 16; w0 += 4) {               // bucket 4: U=16, vj -> accv
        chunk_load(sm, W3, B3, tid, 2816, 16, 16, w0);
        float a0=0,a1=0,a2=0;
        for (int u0 = 0; u0 < 16; u0 += 4) {
            float cs[4]; dot4<16>(sm, frp, wp, u0, cs[0],cs[1],cs[2],cs[3]);
            #pragma unroll
            for (int j = 0; j < 4; ++j) {
                int u = u0+j;
                a0 = fmaf(sm->vj[(u*3+0)*64+e],cs[j],a0);
                a1 = fmaf(sm->vj[(u*3+1)*64+e],cs[j],a1);
                a2 = fmaf(sm->vj[(u*3+2)*64+e],cs[j],a2);
            }
        }
        sm->accv[((w0+wp)*3+0)*64+e] += a0;
        sm->accv[((w0+wp)*3+1)*64+e] += a1;
        sm->accv[((w0+wp)*3+2)*64+e] += a2;
    }
    for (int w0 = 0; w0 < 16; w0 += 4) {               // bucket 5: U=16, q5 -> accv
        chunk_load(sm, W3, B3, tid, 3072, 16, 16, w0);
        float a0=0,a1=0,a2=0;
        for (int u0 = 0; u0 < 16; u0 += 4) {
            float cs[4]; dot4<16>(sm, frp, wp, u0, cs[0],cs[1],cs[2],cs[3]);
            #pragma unroll
            for (int j = 0; j < 4; ++j) {
                int u = u0+j;
                a0 = fmaf(sm->q5[(u*3+0)*64+e],cs[j],a0);
                a1 = fmaf(sm->q5[(u*3+1)*64+e],cs[j],a1);
                a2 = fmaf(sm->q5[(u*3+2)*64+e],cs[j],a2);
            }
        }
        sm->accv[((w0+wp)*3+0)*64+e] += a0;
        sm->accv[((w0+wp)*3+1)*64+e] += a1;
        sm->accv[((w0+wp)*3+2)*64+e] += a2;
    }
    __syncthreads();

    const float SS = 0.029462782549439483f;  // 1/sqrt(48*24)
    const float SV = 0.025515518153991442f;  // 1/sqrt(64*24)
    int dd = sm->dsts[e];
    for (int c = wp*24; c < wp*24+24; ++c) {
        float val;
        if (c < 48) val = sm->accs[c*64+e]*SS;
        else {
            int cc = c-48, w = cc/3, i = cc-w*3;
            val = (sm->accv[cc*64+e] + sm->y1[i*64+e]*sm->t3[w*64+e])*SV;
        }
        atomicAdd(&g_agg[dd*AGGD+c], val);
    }
}

__global__ void k_gate() {
    int idx = blockIdx.x*blockDim.x + threadIdx.x;
    if (idx >= N_NODES*HID) return;
    int n = idx/HID, c = idx - n*HID;
    float add;
    if (c < 32) {
        float a = g_agg[n*AGGD+c];
        add = a/(1.f+expf(-a));
    } else {
        int cc = c-32, w = cc/3;
        float gg = g_agg[n*AGGD+32+w];
        add = g_agg[n*AGGD+48+cc]/(1.f+expf(-gg));
    }
    g_h[idx] = g_h[idx] + g_xself[idx] + add;
}

__global__ void k_out(const float* __restrict__ proj, float* __restrict__ out) {
    int idx = blockIdx.x*blockDim.x + threadIdx.x;
    if (idx >= N_NODES*32) return;
    int n = idx >> 5, j = idx & 31;
    float a = 0.f;
    #pragma unroll
    for (int u = 0; u < 32; ++u) a = fmaf(g_h[n*HID+u], proj[u*32+j], a);
    out[idx] = a*0.17677669529663687f;
}

extern "C" void kernel_launch(void* const* d_in, const int* in_sizes, int n_in,
                              void* d_out, int out_size) {
    const float* x      = (const float*)d_in[0];
    const float* pos    = (const float*)d_in[1];
    const int*   ei     = (const int*)  d_in[2];
    const float* embed  = (const float*)d_in[3];
    const float* proj   = (const float*)d_in[4];
    const float* lin_ws = (const float*)d_in[5];
    const float* lin_wv = (const float*)d_in[6];
    const float* sc_ws  = (const float*)d_in[7];
    const float* sc_wv  = (const float*)d_in[8];
    const float* w1     = (const float*)d_in[9];
    const float* b1     = (const float*)d_in[10];
    const float* w2     = (const float*)d_in[11];
    const float* b2     = (const float*)d_in[12];
    const float* w3     = (const float*)d_in[13];
    const float* b3     = (const float*)d_in[14];

    cudaFuncSetAttribute(k_msg, cudaFuncAttributeMaxDynamicSharedMemorySize, (int)sizeof(SmemK3));

    k_geo<<<192, 256>>>(pos, ei);
    k_init<<<640, 256>>>(x, embed);
    for (int l = 0; l < 4; ++l) {
        k_nodelin<<<8, 256>>>(lin_ws + l*1024, lin_wv + l*256, sc_ws + l*1024, sc_wv + l*256);
        k_radial<<<768, 256>>>(w1 + l*512, b1 + l*64, w2 + l*4096, b2 + l*64);
        k_zero<<<768, 256>>>();
        k_msg<<<768, 256, sizeof(SmemK3)>>>(ei, w3 + l*64*WN, b3 + l*WN);
        k_gate<<<640, 256>>>();
    }
    k_out<<<256, 256>>>(proj, (float*)d_out);
}

// round 10
// speedup vs baseline: 1.2002x; 1.1505x over previous
#include <cuda_runtime.h>
#include <math.h>

#define N_NODES 2048
#define N_EDGES 49152
#define HID     80
#define AGGD    96
#define WN      3328
#define EPB     128

__device__ float g_geo[N_EDGES * 20];
__device__ float g_f2 [4L * N_EDGES * 64];
__device__ float g_h    [N_NODES * HID];
__device__ float g_hx   [N_NODES * HID];
__device__ float g_xself[N_NODES * HID];
__device__ float g_agg  [N_NODES * AGGD];

typedef unsigned long long u64;
__device__ __forceinline__ u64 fma2(u64 a, u64 b, u64 c) {
    u64 d; asm("fma.rn.f32x2 %0, %1, %2, %3;" : "=l"(d) : "l"(a), "l"(b), "l"(c)); return d;
}
__device__ __forceinline__ float lo2(u64 v){ return __uint_as_float((unsigned)v); }
__device__ __forceinline__ float hi2(u64 v){ return __uint_as_float((unsigned)(v>>32)); }

// ---- fused geometry + embed-init ----
__global__ void kA(const float* __restrict__ pos, const int* __restrict__ ei,
                   const float* __restrict__ x, const float* __restrict__ ew) {
    if (blockIdx.x < 192) {
        int e = blockIdx.x*256 + threadIdx.x;
        int s = ei[e], d = ei[N_EDGES + e];
        float rx = pos[d*3+0]-pos[s*3+0], ry = pos[d*3+1]-pos[s*3+1], rz = pos[d*3+2]-pos[s*3+2];
        float r = fmaxf(sqrtf(rx*rx+ry*ry+rz*rz), 1e-6f);
        float inv = 1.f/r;
        float dx = rx*inv, dy = ry*inv, dz = rz*inv;
        float* g = g_geo + e*20;
        const float s3 = 1.7320508075688772f;
        g[0]=s3*dx; g[1]=s3*dy; g[2]=s3*dz;
        const float c15 = 3.872983346207417f;
        float y20=c15*dx*dy, y21=c15*dy*dz, y22=1.1180339887498949f*(3.f*dz*dz-1.f);
        float y23=c15*dx*dz, y24=0.5f*c15*(dx*dx-dy*dy);
        const float s2=0.7071067811865476f, s6=0.4082482904638631f, q=0.7745966692414834f;
        g[3]=q*(-s6*y22+s2*y24); g[4]=q*(-s6*y22-s2*y24); g[5]=q*(2.f*s6*y22);
        g[6]=q*s2*y20; g[7]=q*s2*y21; g[8]=q*s2*y23;
        float u = r*(1.f/6.f);
        float u3=u*u*u, u6=u3*u3, u7=u6*u, u8=u7*u;
        float fc = (u<1.f) ? (1.f-28.f*u6+48.f*u7-21.f*u8) : 0.f;
        float pref = 0.5773502691896258f*inv*fc;
        float pir = 3.14159265358979323846f*r*(1.f/6.f);
        #pragma unroll
        for (int n = 1; n <= 8; ++n) g[8+n] = pref*sinf((float)n*pir);
    } else {
        int idx = (blockIdx.x-192)*256 + threadIdx.x;
        if (idx >= N_NODES*HID) return;
        int n = idx/HID, c = idx - n*HID;
        float v = 0.f;
        if (c < 32) {
            float a = 0.f;
            #pragma unroll
            for (int u = 0; u < 16; ++u) a = fmaf(x[n*16+u], ew[u*32+c], a);
            v = a*0.25f;
        }
        g_h[idx] = v;
    }
}

// ---- radial MLP, all 4 layers in one launch ----
__global__ __launch_bounds__(256)
void k_radial4(const float* __restrict__ W1, const float* __restrict__ B1,
               const float* __restrict__ W2, const float* __restrict__ B2) {
    __shared__ float w1s[512], b1s[64], w2s[4096], b2s[64];
    int tid = threadIdx.x;
    int l = blockIdx.x / 192;
    int e = (blockIdx.x - l*192)*256 + tid;
    const float* W1l = W1 + l*512; const float* W2l = W2 + l*4096;
    for (int i = tid; i < 512;  i += 256) w1s[i]=W1l[i];
    for (int i = tid; i < 4096; i += 256) w2s[i]=W2l[i];
    if (tid < 64) { b1s[tid]=B1[l*64+tid]; b2s[tid]=B2[l*64+tid]; }
    __syncthreads();
    float rbf[8];
    #pragma unroll
    for (int n = 0; n < 8; ++n) rbf[n] = g_geo[e*20+9+n];
    float f1[64];
    #pragma unroll
    for (int o = 0; o < 64; ++o) {
        float a = b1s[o];
        #pragma unroll
        for (int n = 0; n < 8; ++n) a = fmaf(rbf[n], w1s[n*64+o], a);
        f1[o] = a/(1.f+__expf(-a));
    }
    float* outp = g_f2 + ((size_t)l*N_EDGES + e)*64;
    for (int o = 0; o < 64; ++o) {
        float a = b2s[o];
        #pragma unroll
        for (int k = 0; k < 64; ++k) a = fmaf(f1[k], w2s[k*64+o], a);
        outp[o] = a/(1.f+__expf(-a));
    }
}

// ---- node linears (8 threads/node) + g_agg zero ----
__global__ void k_nodelin(const float* __restrict__ Ws, const float* __restrict__ Wv,
                          const float* __restrict__ Ss, const float* __restrict__ Sv) {
    __shared__ float ws_[1024], wv_[256], ss_[1024], sv_[256];
    int tid = threadIdx.x;
    int gid = blockIdx.x*256 + tid;
    for (int i = gid; i < N_NODES*AGGD; i += 64*256) g_agg[i] = 0.f;
    for (int i = tid; i < 1024; i += 256) { ws_[i]=Ws[i]; ss_[i]=Ss[i]; }
    if (tid < 256) { wv_[tid]=Wv[tid]; sv_[tid]=Sv[tid]; }
    __syncthreads();
    int n = gid >> 3, slot = gid & 7;
    float hs[32], hv[48];
    #pragma unroll
    for (int i = 0; i < 32; ++i) hs[i] = g_h[n*HID+i];
    #pragma unroll
    for (int i = 0; i < 48; ++i) hv[i] = g_h[n*HID+32+i];
    const float is = 0.17677669529663687f, iv = 0.25f;
    #pragma unroll
    for (int c4 = 0; c4 < 4; ++c4) {
        int w = slot*4 + c4;
        float a=0.f, b=0.f;
        #pragma unroll
        for (int u = 0; u < 32; ++u) { a=fmaf(hs[u],ws_[u*32+w],a); b=fmaf(hs[u],ss_[u*32+w],b); }
        g_hx[n*HID+w]=a*is; g_xself[n*HID+w]=b*is;
    }
    #pragma unroll
    for (int c2 = 0; c2 < 2; ++c2) {
        int w = slot*2 + c2;
        float a0=0,a1=0,a2=0,b0=0,b1=0,b2=0;
        #pragma unroll
        for (int u = 0; u < 16; ++u) {
            float wl=wv_[u*16+w], sl=sv_[u*16+w];
            a0=fmaf(hv[u*3+0],wl,a0); a1=fmaf(hv[u*3+1],wl,a1); a2=fmaf(hv[u*3+2],wl,a2);
            b0=fmaf(hv[u*3+0],sl,b0); b1=fmaf(hv[u*3+1],sl,b1); b2=fmaf(hv[u*3+2],sl,b2);
        }
        g_hx[n*HID+32+w*3+0]=a0*iv; g_hx[n*HID+32+w*3+1]=a1*iv; g_hx[n*HID+32+w*3+2]=a2*iv;
        g_xself[n*HID+32+w*3+0]=b0*iv; g_xself[n*HID+32+w*3+1]=b1*iv; g_xself[n*HID+32+w*3+2]=b2*iv;
    }
}

// ---- fused W3-gen + message + scatter ----
struct SmemK3 {
    float Wc[4096];      // [k2 32][w'4][u16][kpar2]
    float b3c[64];       // [w'4][u16]
    float sj[32*EPB];
    float p2[16*EPB];
    float vj[48*EPB];
    float q5[48*EPB];
    float y1[3*EPB];
    float Mq[6*EPB];
    float t3[16*EPB];
    float accs[48*EPB];
    float accv[48*EPB];
    int srcs[EPB];
    int dsts[EPB];
};

__device__ __forceinline__ void dotc(const SmemK3* sm, const u64 (&frp)[32], int wp, int u0,
                                     float (&c)[4]) {
    u64 a0=0ULL, a1=0ULL, a2=0ULL, a3=0ULL;
    const float* basep = sm->Wc + (wp*16 + u0)*2;
    #pragma unroll
    for (int k2 = 0; k2 < 32; ++k2) {
        const float* p = basep + k2*128;
        ulonglong2 w01 = *(const ulonglong2*)p;
        ulonglong2 w23 = *(const ulonglong2*)(p+4);
        u64 f = frp[k2];
        a0 = fma2(f, w01.x, a0); a1 = fma2(f, w01.y, a1);
        a2 = fma2(f, w23.x, a2); a3 = fma2(f, w23.y, a3);
    }
    c[0] = sm->b3c[wp*16+u0+0] + lo2(a0) + hi2(a0);
    c[1] = sm->b3c[wp*16+u0+1] + lo2(a1) + hi2(a1);
    c[2] = sm->b3c[wp*16+u0+2] + lo2(a2) + hi2(a2);
    c[3] = sm->b3c[wp*16+u0+3] + lo2(a3) + hi2(a3);
}

__global__ __launch_bounds__(512, 1)
void k_msg(int l, const int* __restrict__ ei,
           const float* __restrict__ W3, const float* __restrict__ B3) {
    extern __shared__ unsigned char smraw[];
    SmemK3* sm = (SmemK3*)smraw;
    int tid = threadIdx.x;
    int e = tid & 127, wp = tid >> 7;
    int e0 = blockIdx.x * EPB;

    float4 pf0, pf1; float bpf = 0.f;
    int k0 = tid >> 4, u0l = tid & 15;
    int g1 = tid + 512, k1 = g1 >> 4, u1l = g1 & 15;

    auto LDGc = [&](int src, int Wst) {
        pf0 = *(const float4*)(W3 + (size_t)k0*WN + src + u0l*Wst);
        pf1 = *(const float4*)(W3 + (size_t)k1*WN + src + u1l*Wst);
        if (tid < 64) bpf = B3[src + (tid & 15)*Wst + (tid >> 4)];
    };
    auto STSc = [&]() {
        float* d0 = sm->Wc + (k0>>1)*128 + u0l*2 + (k0&1);
        d0[0]=pf0.x; d0[32]=pf0.y; d0[64]=pf0.z; d0[96]=pf0.w;
        float* d1 = sm->Wc + (k1>>1)*128 + u1l*2 + (k1&1);
        d1[0]=pf1.x; d1[32]=pf1.y; d1[64]=pf1.z; d1[96]=pf1.w;
        if (tid < 64) sm->b3c[tid] = bpf;
    };

    if (tid < EPB) { sm->srcs[tid] = ei[e0+tid]; sm->dsts[tid] = ei[N_EDGES+e0+tid]; }
    __syncthreads();
    for (int i = tid; i < EPB*80; i += 512) {
        int ee = i/80, c = i - ee*80;
        float v = g_hx[sm->srcs[ee]*HID + c];
        if (c < 32) sm->sj[c*EPB+ee] = v; else sm->vj[(c-32)*EPB+ee] = v;
    }
    for (int i = tid; i < EPB*9; i += 512) {
        int ee = i/9, c = i - ee*9;
        float v = g_geo[(e0+ee)*20 + c];
        if (c < 3) sm->y1[c*EPB+ee] = v; else sm->Mq[(c-3)*EPB+ee] = v;
    }
    { float* z = sm->t3; for (int i = tid; i < 14336; i += 512) z[i] = 0.f; }
    u64 frp[32];
    {
        const ulonglong2* fp = (const ulonglong2*)(g_f2 + ((size_t)l*N_EDGES + e0 + e)*64);
        #pragma unroll
        for (int q = 0; q < 16; ++q) { ulonglong2 v = fp[q]; frp[2*q]=v.x; frp[2*q+1]=v.y; }
    }
    __syncthreads();
    for (int i = tid; i < EPB*16; i += 512) {
        int ee = i & 127, u = i >> 7;
        float v0 = sm->vj[(u*3+0)*EPB+ee], v1 = sm->vj[(u*3+1)*EPB+ee], v2 = sm->vj[(u*3+2)*EPB+ee];
        float y0 = sm->y1[0*EPB+ee], yy = sm->y1[EPB+ee], yz = sm->y1[2*EPB+ee];
        sm->p2[u*EPB+ee] = (v0*y0+v1*yy+v2*yz)*0.5773502691896258f;
        float M00=sm->Mq[0*EPB+ee],M11=sm->Mq[EPB+ee],M22=sm->Mq[2*EPB+ee];
        float M01=sm->Mq[3*EPB+ee],M12=sm->Mq[4*EPB+ee],M02=sm->Mq[5*EPB+ee];
        sm->q5[(u*3+0)*EPB+ee]=v0*M00+v1*M01+v2*M02;
        sm->q5[(u*3+1)*EPB+ee]=v0*M01+v1*M11+v2*M12;
        sm->q5[(u*3+2)*EPB+ee]=v0*M02+v1*M12+v2*M22;
    }
    LDGc(0, 48);               // prefetch first chunk (b1: uh=0, w0=0)
    __syncthreads();

    // bucket 1: U=32 (2 u-halves), W=48, sj -> accs
    for (int w0 = 0; w0 < 48; w0 += 4)
    for (int uh = 0; uh < 2; ++uh) {
        STSc(); __syncthreads();
        int nuh = uh+1, nw0 = w0; if (nuh==2){nuh=0;nw0+=4;}
        if (nw0 < 48) LDGc(nuh*768 + nw0, 48); else LDGc(1536, 48);
        float a = 0.f; int uoff = uh*16;
        #pragma unroll
        for (int u0 = 0; u0 < 16; u0 += 4) {
            float c[4]; dotc(sm, frp, wp, u0, c);
            #pragma unroll
            for (int j = 0; j < 4; ++j) a = fmaf(sm->sj[(uoff+u0+j)*EPB+e], c[j], a);
        }
        sm->accs[(w0+wp)*EPB+e] += a;
        __syncthreads();
    }
    // bucket 2: U=16, W=48, p2 -> accs
    for (int w0 = 0; w0 < 48; w0 += 4) {
        STSc(); __syncthreads();
        int nw0 = w0+4;
        if (nw0 < 48) LDGc(1536+nw0, 48); else LDGc(2304, 16);
        float a = 0.f;
        #pragma unroll
        for (int u0 = 0; u0 < 16; u0 += 4) {
            float c[4]; dotc(sm, frp, wp, u0, c);
            #pragma unroll
            for (int j = 0; j < 4; ++j) a = fmaf(sm->p2[(u0+j)*EPB+e], c[j], a);
        }
        sm->accs[(w0+wp)*EPB+e] += a;
        __syncthreads();
    }
    // bucket 3: U=32 (2 u-halves), W=16, sj -> t3
    for (int w0 = 0; w0 < 16; w0 += 4)
    for (int uh = 0; uh < 2; ++uh) {
        STSc(); __syncthreads();
        int nuh = uh+1, nw0 = w0; if (nuh==2){nuh=0;nw0+=4;}
        if (nw0 < 16) LDGc(2304 + nuh*256 + nw0, 16); else LDGc(2816, 16);
        float a = 0.f; int uoff = uh*16;
        #pragma unroll
        for (int u0 = 0; u0 < 16; u0 += 4) {
            float c[4]; dotc(sm, frp, wp, u0, c);
            #pragma unroll
            for (int j = 0; j < 4; ++j) a = fmaf(sm->sj[(uoff+u0+j)*EPB+e], c[j], a);
        }
        sm->t3[(w0+wp)*EPB+e] += a;
        __syncthreads();
    }
    // bucket 4: U=16, W=16, vj -> accv
    for (int w0 = 0; w0 < 16; w0 += 4) {
        STSc(); __syncthreads();
        int nw0 = w0+4;
        if (nw0 < 16) LDGc(2816+nw0, 16); else LDGc(3072, 16);
        float a0=0,a1=0,a2=0;
        #pragma unroll
        for (int u0 = 0; u0 < 16; u0 += 4) {
            float c[4]; dotc(sm, frp, wp, u0, c);
            #pragma unroll
            for (int j = 0; j < 4; ++j) {
                int u = u0+j;
                a0 = fmaf(sm->vj[(u*3+0)*EPB+e], c[j], a0);
                a1 = fmaf(sm->vj[(u*3+1)*EPB+e], c[j], a1);
                a2 = fmaf(sm->vj[(u*3+2)*EPB+e], c[j], a2);
            }
        }
        sm->accv[((w0+wp)*3+0)*EPB+e] += a0;
        sm->accv[((w0+wp)*3+1)*EPB+e] += a1;
        sm->accv[((w0+wp)*3+2)*EPB+e] += a2;
        __syncthreads();
    }
    // bucket 5: U=16, W=16, q5 -> accv
    for (int w0 = 0; w0 < 16; w0 += 4) {
        STSc(); __syncthreads();
        int nw0 = w0+4;
        if (nw0 < 16) LDGc(3072+nw0, 16);
        float a0=0,a1=0,a2=0;
        #pragma unroll
        for (int u0 = 0; u0 < 16; u0 += 4) {
            float c[4]; dotc(sm, frp, wp, u0, c);
            #pragma unroll
            for (int j = 0; j < 4; ++j) {
                int u = u0+j;
                a0 = fmaf(sm->q5[(u*3+0)*EPB+e], c[j], a0);
                a1 = fmaf(sm->q5[(u*3+1)*EPB+e], c[j], a1);
                a2 = fmaf(sm->q5[(u*3+2)*EPB+e], c[j], a2);
            }
        }
        sm->accv[((w0+wp)*3+0)*EPB+e] += a0;
        sm->accv[((w0+wp)*3+1)*EPB+e] += a1;
        sm->accv[((w0+wp)*3+2)*EPB+e] += a2;
        __syncthreads();
    }

    const float SS = 0.029462782549439483f;  // 1/sqrt(48*24)
    const float SV = 0.025515518153991442f;  // 1/sqrt(64*24)
    int dd = sm->dsts[e];
    for (int c = wp*24; c < wp*24+24; ++c) {
        float val;
        if (c < 48) val = sm->accs[c*EPB+e]*SS;
        else {
            int cc = c-48, w = cc/3, i = cc-w*3;
            val = (sm->accv[cc*EPB+e] + sm->y1[i*EPB+e]*sm->t3[w*EPB+e])*SV;
        }
        atomicAdd(&g_agg[dd*AGGD+c], val);
    }
}

__global__ void k_gate() {
    int idx = blockIdx.x*blockDim.x + threadIdx.x;
    if (idx >= N_NODES*HID) return;
    int n = idx/HID, c = idx - n*HID;
    float add;
    if (c < 32) {
        float a = g_agg[n*AGGD+c];
        add = a/(1.f+expf(-a));
    } else {
        int cc = c-32, w = cc/3;
        float gg = g_agg[n*AGGD+32+w];
        add = g_agg[n*AGGD+48+cc]/(1.f+expf(-gg));
    }
    g_h[idx] = g_h[idx] + g_xself[idx] + add;
}

__global__ void k_out(const float* __restrict__ proj, float* __restrict__ out) {
    int idx = blockIdx.x*blockDim.x + threadIdx.x;
    if (idx >= N_NODES*32) return;
    int n = idx >> 5, j = idx & 31;
    float a = 0.f;
    #pragma unroll
    for (int u = 0; u < 32; ++u) a = fmaf(g_h[n*HID+u], proj[u*32+j], a);
    out[idx] = a*0.17677669529663687f;
}

extern "C" void kernel_launch(void* const* d_in, const int* in_sizes, int n_in,
                              void* d_out, int out_size) {
    const float* x      = (const float*)d_in[0];
    const float* pos    = (const float*)d_in[1];
    const int*   ei     = (const int*)  d_in[2];
    const float* embed  = (const float*)d_in[3];
    const float* proj   = (const float*)d_in[4];
    const float* lin_ws = (const float*)d_in[5];
    const float* lin_wv = (const float*)d_in[6];
    const float* sc_ws  = (const float*)d_in[7];
    const float* sc_wv  = (const float*)d_in[8];
    const float* w1     = (const float*)d_in[9];
    const float* b1     = (const float*)d_in[10];
    const float* w2     = (const float*)d_in[11];
    const float* b2     = (const float*)d_in[12];
    const float* w3     = (const float*)d_in[13];
    const float* b3     = (const float*)d_in[14];

    cudaFuncSetAttribute(k_msg, cudaFuncAttributeMaxDynamicSharedMemorySize, (int)sizeof(SmemK3));

    kA<<<832, 256>>>(pos, ei, x, embed);
    k_radial4<<<768, 256>>>(w1, b1, w2, b2);
    for (int l = 0; l < 4; ++l) {
        k_nodelin<<<64, 256>>>(lin_ws + l*1024, lin_wv + l*256, sc_ws + l*1024, sc_wv + l*256);
        k_msg<<<384, 512, sizeof(SmemK3)>>>(l, ei, w3 + l*64*WN, b3 + l*WN);
        k_gate<<<640, 256>>>();
    }
    k_out<<<256, 256>>>(proj, (float*)d_out);
}

// round 12
// speedup vs baseline: 2.0248x; 1.6870x over previous
#include <cuda_runtime.h>
#include <cuda_bf16.h>
#include <math.h>
#include <stdint.h>

#define N_NODES 2048
#define N_EDGES 49152
#define HID     80
#define AGGD    96
#define WN      3328
#define EPB     128

__device__ float g_geo[N_EDGES * 20];
__device__ float g_f2 [4L * N_EDGES * 64];
__device__ float g_h    [N_NODES * HID];
__device__ float g_hx   [N_NODES * HID];
__device__ float g_xself[N_NODES * HID];
__device__ float g_agg  [N_NODES * AGGD];

__device__ __forceinline__ unsigned s2u(const void* p) {
    unsigned a;
    asm("{ .reg .u64 t; cvta.to.shared.u64 t, %1; cvt.u32.u64 %0, t; }" : "=r"(a) : "l"(p));
    return a;
}
__device__ __forceinline__ void ldsm4(uint32_t* r, unsigned addr) {
    asm volatile("ldmatrix.sync.aligned.m8n8.x4.shared.b16 {%0,%1,%2,%3}, [%4];"
                 : "=r"(r[0]), "=r"(r[1]), "=r"(r[2]), "=r"(r[3]) : "r"(addr));
}
__device__ __forceinline__ void mma16816(float* c, const uint32_t* a, uint32_t b0, uint32_t b1) {
    asm volatile("mma.sync.aligned.m16n8k16.row.col.f32.bf16.bf16.f32 "
                 "{%0,%1,%2,%3}, {%4,%5,%6,%7}, {%8,%9}, {%0,%1,%2,%3};"
                 : "+f"(c[0]), "+f"(c[1]), "+f"(c[2]), "+f"(c[3])
                 : "r"(a[0]), "r"(a[1]), "r"(a[2]), "r"(a[3]), "r"(b0), "r"(b1));
}
__device__ __forceinline__ unsigned pk(float a, float b) {
    __nv_bfloat162 t = __floats2bfloat162_rn(a, b);
    return *reinterpret_cast<unsigned*>(&t);
}

// ---- chunk tables (26 chunks x 128 slots) ----
__device__ const int cb_[26]  = {0,0,0,0,0,0,0,0,0,0,0,0, 1536,1536,1536,1536,1536,1536,
                                 2304,2304,2304,2304, 2816,2816, 3072,3072};
__device__ const int cw_[26]  = {48,48,48,48,48,48,48,48,48,48,48,48, 48,48,48,48,48,48,
                                 16,16,16,16, 16,16, 16,16};
__device__ const int cnu_[26] = {32,32,32,32,32,32,32,32,32,32,32,32, 16,16,16,16,16,16,
                                 32,32,32,32, 16,16, 16,16};
__device__ const int cwb_[26] = {0,4,8,12,16,20,24,28,32,36,40,44, 0,8,16,24,32,40,
                                 0,4,8,12, 0,8, 0,8};
__device__ const int cbk_[26] = {0,0,0,0,0,0,0,0,0,0,0,0, 1,1,1,1,1,1, 2,2,2,2, 3,3, 4,4};

// ---------------- fused geometry + embed-init ----------------
__global__ void kA(const float* __restrict__ pos, const int* __restrict__ ei,
                   const float* __restrict__ x, const float* __restrict__ ew) {
    if (blockIdx.x < 192) {
        int e = blockIdx.x*256 + threadIdx.x;
        int s = ei[e], d = ei[N_EDGES + e];
        float rx = pos[d*3+0]-pos[s*3+0], ry = pos[d*3+1]-pos[s*3+1], rz = pos[d*3+2]-pos[s*3+2];
        float r = fmaxf(sqrtf(rx*rx+ry*ry+rz*rz), 1e-6f);
        float inv = 1.f/r;
        float dx = rx*inv, dy = ry*inv, dz = rz*inv;
        float* g = g_geo + e*20;
        const float s3 = 1.7320508075688772f;
        g[0]=s3*dx; g[1]=s3*dy; g[2]=s3*dz;
        const float c15 = 3.872983346207417f;
        float y20=c15*dx*dy, y21=c15*dy*dz, y22=1.1180339887498949f*(3.f*dz*dz-1.f);
        float y23=c15*dx*dz, y24=0.5f*c15*(dx*dx-dy*dy);
        const float s2=0.7071067811865476f, s6=0.4082482904638631f, q=0.7745966692414834f;
        g[3]=q*(-s6*y22+s2*y24); g[4]=q*(-s6*y22-s2*y24); g[5]=q*(2.f*s6*y22);
        g[6]=q*s2*y20; g[7]=q*s2*y21; g[8]=q*s2*y23;
        float u = r*(1.f/6.f);
        float u3=u*u*u, u6=u3*u3, u7=u6*u, u8=u7*u;
        float fc = (u<1.f) ? (1.f-28.f*u6+48.f*u7-21.f*u8) : 0.f;
        float pref = 0.5773502691896258f*inv*fc;
        float pir = 3.14159265358979323846f*r*(1.f/6.f);
        #pragma unroll
        for (int n = 1; n <= 8; ++n) g[8+n] = pref*sinf((float)n*pir);
    } else {
        int idx = (blockIdx.x-192)*256 + threadIdx.x;
        if (idx >= N_NODES*HID) return;
        int n = idx/HID, c = idx - n*HID;
        float v = 0.f;
        if (c < 32) {
            float a = 0.f;
            #pragma unroll
            for (int u = 0; u < 16; ++u) a = fmaf(x[n*16+u], ew[u*32+c], a);
            v = a*0.25f;
        }
        g_h[idx] = v;
    }
}

// ---------------- radial MLP (all 4 layers) ----------------
__global__ __launch_bounds__(256)
void k_radial4(const float* __restrict__ W1, const float* __restrict__ B1,
               const float* __restrict__ W2, const float* __restrict__ B2) {
    __shared__ float w1s[512], b1s[64], w2s[4096], b2s[64];
    int tid = threadIdx.x;
    int l = blockIdx.x / 192;
    int e = (blockIdx.x - l*192)*256 + tid;
    const float* W1l = W1 + l*512; const float* W2l = W2 + l*4096;
    for (int i = tid; i < 512;  i += 256) w1s[i]=W1l[i];
    for (int i = tid; i < 4096; i += 256) w2s[i]=W2l[i];
    if (tid < 64) { b1s[tid]=B1[l*64+tid]; b2s[tid]=B2[l*64+tid]; }
    __syncthreads();
    float rbf[8];
    #pragma unroll
    for (int n = 0; n < 8; ++n) rbf[n] = g_geo[e*20+9+n];
    float f1[64];
    #pragma unroll
    for (int o = 0; o < 64; ++o) {
        float a = b1s[o];
        #pragma unroll
        for (int n = 0; n < 8; ++n) a = fmaf(rbf[n], w1s[n*64+o], a);
        f1[o] = a/(1.f+__expf(-a));
    }
    float* outp = g_f2 + ((size_t)l*N_EDGES + e)*64;
    for (int o = 0; o < 64; ++o) {
        float a = b2s[o];
        #pragma unroll
        for (int k = 0; k < 64; ++k) a = fmaf(f1[k], w2s[k*64+o], a);
        outp[o] = a/(1.f+__expf(-a));
    }
}

// ---------------- node linears + agg zero ----------------
__global__ void k_nodelin(const float* __restrict__ Ws, const float* __restrict__ Wv,
                          const float* __restrict__ Ss, const float* __restrict__ Sv) {
    __shared__ float ws_[1024], wv_[256], ss_[1024], sv_[256];
    int tid = threadIdx.x;
    int gid = blockIdx.x*256 + tid;
    for (int i = gid; i < N_NODES*AGGD; i += 64*256) g_agg[i] = 0.f;
    for (int i = tid; i < 1024; i += 256) { ws_[i]=Ws[i]; ss_[i]=Ss[i]; }
    if (tid < 256) { wv_[tid]=Wv[tid]; sv_[tid]=Sv[tid]; }
    __syncthreads();
    int n = gid >> 3, slot = gid & 7;
    float hs[32], hv[48];
    #pragma unroll
    for (int i = 0; i < 32; ++i) hs[i] = g_h[n*HID+i];
    #pragma unroll
    for (int i = 0; i < 48; ++i) hv[i] = g_h[n*HID+32+i];
    const float is = 0.17677669529663687f, iv = 0.25f;
    #pragma unroll
    for (int c4 = 0; c4 < 4; ++c4) {
        int w = slot*4 + c4;
        float a=0.f, b=0.f;
        #pragma unroll
        for (int u = 0; u < 32; ++u) { a=fmaf(hs[u],ws_[u*32+w],a); b=fmaf(hs[u],ss_[u*32+w],b); }
        g_hx[n*HID+w]=a*is; g_xself[n*HID+w]=b*is;
    }
    #pragma unroll
    for (int c2 = 0; c2 < 2; ++c2) {
        int w = slot*2 + c2;
        float a0=0,a1=0,a2=0,b0=0,b1=0,b2=0;
        #pragma unroll
        for (int u = 0; u < 16; ++u) {
            float wl=wv_[u*16+w], sl=sv_[u*16+w];
            a0=fmaf(hv[u*3+0],wl,a0); a1=fmaf(hv[u*3+1],wl,a1); a2=fmaf(hv[u*3+2],wl,a2);
            b0=fmaf(hv[u*3+0],sl,b0); b1=fmaf(hv[u*3+1],sl,b1); b2=fmaf(hv[u*3+2],sl,b2);
        }
        g_hx[n*HID+32+w*3+0]=a0*iv; g_hx[n*HID+32+w*3+1]=a1*iv; g_hx[n*HID+32+w*3+2]=a2*iv;
        g_xself[n*HID+32+w*3+0]=b0*iv; g_xself[n*HID+32+w*3+1]=b1*iv; g_xself[n*HID+32+w*3+2]=b2*iv;
    }
}

// ---------------- k_msg: warp-MMA W3-gen + message + scatter ----------------
#define RP 72   // bf16 row pitch (144 B)

struct SmemT {
    __nv_bfloat16 Ah[128*RP];
    __nv_bfloat16 Al[128*RP];
    __nv_bfloat16 Bh[128*RP];
    __nv_bfloat16 Bl[128*RP];
    float bias[128];
    float sj[32*EPB];
    float p2[16*EPB];
    float vj[48*EPB];
    float q5[48*EPB];
    float y1[3*EPB];
    float Mq[6*EPB];
    float t3[16*EPB];
    float accs[48*EPB];
    float accv[48*EPB];
    int srcs[EPB];
    int dsts[EPB];
};

__global__ __launch_bounds__(512, 1)
void k_msg(int l, const int* __restrict__ ei,
           const float* __restrict__ W3, const float* __restrict__ B3) {
    extern __shared__ unsigned char smraw[];
    SmemT* sm = (SmemT*)smraw;
    int tid = threadIdx.x;
    int wid = tid >> 5, lid = tid & 31;
    int e0 = blockIdx.x * EPB;

    if (tid < EPB) { sm->srcs[tid] = ei[e0+tid]; sm->dsts[tid] = ei[N_EDGES+e0+tid]; }
    __syncthreads();

    for (int i = tid; i < EPB*80; i += 512) {
        int ee = i/80, c = i - ee*80;
        float v = g_hx[sm->srcs[ee]*HID + c];
        if (c < 32) sm->sj[c*EPB+ee] = v; else sm->vj[(c-32)*EPB+ee] = v;
    }
    for (int i = tid; i < EPB*9; i += 512) {
        int ee = i/9, c = i - ee*9;
        float v = g_geo[(e0+ee)*20 + c];
        if (c < 3) sm->y1[c*EPB+ee] = v; else sm->Mq[(c-3)*EPB+ee] = v;
    }
    // A tiles: f2 split hi/lo (once per block)
    for (int t = tid; t < 4096; t += 512) {
        int kp = t & 31, r = t >> 5;
        const float* f2row = g_f2 + ((size_t)l*N_EDGES + e0 + r)*64;
        float2 v = *(const float2*)(f2row + 2*kp);
        float h0 = __bfloat162float(__float2bfloat16(v.x));
        float h1 = __bfloat162float(__float2bfloat16(v.y));
        unsigned idx = (unsigned)(r*RP + kp*2);
        *(unsigned*)(sm->Ah + idx) = pk(v.x, v.y);
        *(unsigned*)(sm->Al + idx) = pk(v.x - h0, v.y - h1);
    }
    __syncthreads();
    for (int i = tid; i < EPB*16; i += 512) {
        int ee = i & 127, u = i >> 7;
        float v0 = sm->vj[(u*3+0)*EPB+ee], v1 = sm->vj[(u*3+1)*EPB+ee], v2 = sm->vj[(u*3+2)*EPB+ee];
        float y0 = sm->y1[0*EPB+ee], yy = sm->y1[EPB+ee], yz = sm->y1[2*EPB+ee];
        sm->p2[u*EPB+ee] = (v0*y0+v1*yy+v2*yz)*0.5773502691896258f;
        float M00=sm->Mq[0*EPB+ee],M11=sm->Mq[EPB+ee],M22=sm->Mq[2*EPB+ee];
        float M01=sm->Mq[3*EPB+ee],M12=sm->Mq[4*EPB+ee],M02=sm->Mq[5*EPB+ee];
        sm->q5[(u*3+0)*EPB+ee]=v0*M00+v1*M01+v2*M02;
        sm->q5[(u*3+1)*EPB+ee]=v0*M01+v1*M11+v2*M12;
        sm->q5[(u*3+2)*EPB+ee]=v0*M02+v1*M12+v2*M22;
    }

    int wq = wid >> 2;                 // col group 0..3
    int rgrp = (wid & 3) * 32;         // edge-row group
    int cg = wq * 32;
    int q = lid >> 2, ln4 = lid & 3;
    unsigned ahB = s2u(sm->Ah), alB = s2u(sm->Al), bhB = s2u(sm->Bh), blB = s2u(sm->Bl);
    unsigned a_off = (unsigned)((rgrp + (lid & 15))*144 + ((lid >> 4)*8)*2);
    unsigned b_off = (unsigned)((cg + ((lid >> 4)*8) + (lid & 7))*144 + (((lid >> 3) & 1)*8)*2);

    for (int c = 0; c < 26; ++c) {
        int base = cb_[c], W = cw_[c], nu = cnu_[c], wb = cwb_[c], bk = cbk_[c];
        // ---- B chunk: split bf16, [slot][k] rows, pitch 72 bf16 ----
        for (int t = tid; t < 1024; t += 512) {
            int kp = t & 31, rem = t >> 5;
            int u, w4;
            if (nu == 32) { u = rem; w4 = 0; } else { u = rem & 15; w4 = rem >> 4; }
            int col = base + u*W + wb + w4*4;
            const float* p0 = W3 + (size_t)(2*kp)*WN + col;
            float4 a = *(const float4*)p0;
            float4 b = *(const float4*)(p0 + WN);
            const float* av = (const float*)&a;
            const float* bv = (const float*)&b;
            #pragma unroll
            for (int j = 0; j < 4; ++j) {
                int s = (nu == 32) ? (j*32 + u) : ((w4*4 + j)*16 + u);
                float x0 = av[j], x1 = bv[j];
                float h0 = __bfloat162float(__float2bfloat16(x0));
                float h1 = __bfloat162float(__float2bfloat16(x1));
                unsigned idx = (unsigned)(s*RP + kp*2);
                *(unsigned*)(sm->Bh + idx) = pk(x0, x1);
                *(unsigned*)(sm->Bl + idx) = pk(x0 - h0, x1 - h1);
            }
        }
        if (tid < 128) {
            int s = tid, u, w4;
            if (nu == 32) { u = s & 31; w4 = s >> 5; }
            else          { u = s & 15; w4 = s >> 4; }
            sm->bias[s] = B3[base + u*W + wb + w4];
        }
        __syncthreads();

        // ---- MMA: 32x32 tile per warp, 3 split terms, k=64 ----
        float acc[2][4][4];
        #pragma unroll
        for (int i = 0; i < 2; ++i)
            #pragma unroll
            for (int j = 0; j < 4; ++j)
                #pragma unroll
                for (int k = 0; k < 4; ++k) acc[i][j][k] = 0.f;
        #pragma unroll
        for (int k0 = 0; k0 < 64; k0 += 16) {
            uint32_t Ah0[4],Ah1[4],Al0[4],Al1[4],Bh0[4],Bh1[4],Bl0[4],Bl1[4];
            ldsm4(Ah0, ahB + a_off + k0*2);
            ldsm4(Ah1, ahB + a_off + 16*144 + k0*2);
            ldsm4(Al0, alB + a_off + k0*2);
            ldsm4(Al1, alB + a_off + 16*144 + k0*2);
            ldsm4(Bh0, bhB + b_off + k0*2);
            ldsm4(Bh1, bhB + b_off + 16*144 + k0*2);
            ldsm4(Bl0, blB + b_off + k0*2);
            ldsm4(Bl1, blB + b_off + 16*144 + k0*2);
            uint32_t* Bhp[4] = {Bh0, Bh0+2, Bh1, Bh1+2};
            uint32_t* Blp[4] = {Bl0, Bl0+2, Bl1, Bl1+2};
            #pragma unroll
            for (int nt = 0; nt < 4; ++nt) {
                mma16816(acc[0][nt], Ah0, Bhp[nt][0], Bhp[nt][1]);
                mma16816(acc[1][nt], Ah1, Bhp[nt][0], Bhp[nt][1]);
                mma16816(acc[0][nt], Ah0, Blp[nt][0], Blp[nt][1]);
                mma16816(acc[1][nt], Ah1, Blp[nt][0], Blp[nt][1]);
                mma16816(acc[0][nt], Al0, Bhp[nt][0], Bhp[nt][1]);
                mma16816(acc[1][nt], Al1, Bhp[nt][0], Bhp[nt][1]);
            }
        }

        // ---- in-register epilogue ----
        float bias8[8];
        #pragma unroll
        for (int nt = 0; nt < 4; ++nt)
            #pragma unroll
            for (int jj = 0; jj < 2; ++jj)
                bias8[nt*2+jj] = sm->bias[cg + nt*8 + ln4*2 + jj];

        if (bk == 0 || bk == 2) {
            #pragma unroll
            for (int i = 0; i < 4; ++i) {
                int er = rgrp + q + i*8;
                float p = 0.f;
                #pragma unroll
                for (int nt = 0; nt < 4; ++nt)
                    #pragma unroll
                    for (int jj = 0; jj < 2; ++jj) {
                        int u = nt*8 + ln4*2 + jj;
                        p = fmaf(acc[i>>1][nt][(i&1)*2+jj] + bias8[nt*2+jj],
                                 sm->sj[u*EPB+er], p);
                    }
                p += __shfl_xor_sync(0xFFFFFFFFu, p, 1);
                p += __shfl_xor_sync(0xFFFFFFFFu, p, 2);
                if (ln4 == 0) {
                    if (bk == 0) sm->accs[(wb+wq)*EPB+er] = p;
                    else         sm->t3[(wb+wq)*EPB+er]   = p;
                }
            }
        } else if (bk == 1) {
            #pragma unroll
            for (int i = 0; i < 4; ++i) {
                int er = rgrp + q + i*8;
                #pragma unroll
                for (int h = 0; h < 2; ++h) {
                    float p = 0.f;
                    #pragma unroll
                    for (int n2 = 0; n2 < 2; ++n2) {
                        int nt = h*2 + n2;
                        #pragma unroll
                        for (int jj = 0; jj < 2; ++jj) {
                            int u = n2*8 + ln4*2 + jj;
                            p = fmaf(acc[i>>1][nt][(i&1)*2+jj] + bias8[nt*2+jj],
                                     sm->p2[u*EPB+er], p);
                        }
                    }
                    p += __shfl_xor_sync(0xFFFFFFFFu, p, 1);
                    p += __shfl_xor_sync(0xFFFFFFFFu, p, 2);
                    if (ln4 == 0) sm->accs[(wb + wq*2 + h)*EPB+er] += p;
                }
            }
        } else {
            const float* ft = (bk == 3) ? sm->vj : sm->q5;
            #pragma unroll
            for (int i = 0; i < 4; ++i) {
                int er = rgrp + q + i*8;
                #pragma unroll
                for (int h = 0; h < 2; ++h) {
                    float a0=0.f, a1=0.f, a2=0.f;
                    #pragma unroll
                    for (int n2 = 0; n2 < 2; ++n2) {
                        int nt = h*2 + n2;
                        #pragma unroll
                        for (int jj = 0; jj < 2; ++jj) {
                            int u = n2*8 + ln4*2 + jj;
                            float b = acc[i>>1][nt][(i&1)*2+jj] + bias8[nt*2+jj];
                            a0 = fmaf(b, ft[(u*3+0)*EPB+er], a0);
                            a1 = fmaf(b, ft[(u*3+1)*EPB+er], a1);
                            a2 = fmaf(b, ft[(u*3+2)*EPB+er], a2);
                        }
                    }
                    a0 += __shfl_xor_sync(0xFFFFFFFFu, a0, 1);
                    a0 += __shfl_xor_sync(0xFFFFFFFFu, a0, 2);
                    a1 += __shfl_xor_sync(0xFFFFFFFFu, a1, 1);
                    a1 += __shfl_xor_sync(0xFFFFFFFFu, a1, 2);
                    a2 += __shfl_xor_sync(0xFFFFFFFFu, a2, 1);
                    a2 += __shfl_xor_sync(0xFFFFFFFFu, a2, 2);
                    if (ln4 == 0) {
                        int w = wb + wq*2 + h;
                        if (bk == 3) {
                            sm->accv[(w*3+0)*EPB+er] = a0;
                            sm->accv[(w*3+1)*EPB+er] = a1;
                            sm->accv[(w*3+2)*EPB+er] = a2;
                        } else {
                            sm->accv[(w*3+0)*EPB+er] += a0;
                            sm->accv[(w*3+1)*EPB+er] += a1;
                            sm->accv[(w*3+2)*EPB+er] += a2;
                        }
                    }
                }
            }
        }
        __syncthreads();
    }

    // ---- finalize + scatter ----
    const float SS = 0.029462782549439483f;  // 1/sqrt(48*24)
    const float SV = 0.025515518153991442f;  // 1/sqrt(64*24)
    int e = tid & 127, wp = tid >> 7;
    int dd = sm->dsts[e];
    for (int c = wp*24; c < wp*24+24; ++c) {
        float val;
        if (c < 48) val = sm->accs[c*EPB+e]*SS;
        else {
            int cc = c-48, w = cc/3, i = cc-w*3;
            val = (sm->accv[cc*EPB+e] + sm->y1[i*EPB+e]*sm->t3[w*EPB+e])*SV;
        }
        atomicAdd(&g_agg[dd*AGGD+c], val);
    }
}

__global__ void k_gate() {
    int idx = blockIdx.x*blockDim.x + threadIdx.x;
    if (idx >= N_NODES*HID) return;
    int n = idx/HID, c = idx - n*HID;
    float add;
    if (c < 32) {
        float a = g_agg[n*AGGD+c];
        add = a/(1.f+expf(-a));
    } else {
        int cc = c-32, w = cc/3;
        float gg = g_agg[n*AGGD+32+w];
        add = g_agg[n*AGGD+48+cc]/(1.f+expf(-gg));
    }
    g_h[idx] = g_h[idx] + g_xself[idx] + add;
}

__global__ void k_out(const float* __restrict__ proj, float* __restrict__ out) {
    int idx = blockIdx.x*blockDim.x + threadIdx.x;
    if (idx >= N_NODES*32) return;
    int n = idx >> 5, j = idx & 31;
    float a = 0.f;
    #pragma unroll
    for (int u = 0; u < 32; ++u) a = fmaf(g_h[n*HID+u], proj[u*32+j], a);
    out[idx] = a*0.17677669529663687f;
}

extern "C" void kernel_launch(void* const* d_in, const int* in_sizes, int n_in,
                              void* d_out, int out_size) {
    const float* x      = (const float*)d_in[0];
    const float* pos    = (const float*)d_in[1];
    const int*   ei     = (const int*)  d_in[2];
    const float* embed  = (const float*)d_in[3];
    const float* proj   = (const float*)d_in[4];
    const float* lin_ws = (const float*)d_in[5];
    const float* lin_wv = (const float*)d_in[6];
    const float* sc_ws  = (const float*)d_in[7];
    const float* sc_wv  = (const float*)d_in[8];
    const float* w1     = (const float*)d_in[9];
    const float* b1     = (const float*)d_in[10];
    const float* w2     = (const float*)d_in[11];
    const float* b2     = (const float*)d_in[12];
    const float* w3     = (const float*)d_in[13];
    const float* b3     = (const float*)d_in[14];

    cudaFuncSetAttribute(k_msg, cudaFuncAttributeMaxDynamicSharedMemorySize, (int)sizeof(SmemT));

    kA<<<832, 256>>>(pos, ei, x, embed);
    k_radial4<<<768, 256>>>(w1, b1, w2, b2);
    for (int l = 0; l < 4; ++l) {
        k_nodelin<<<64, 256>>>(lin_ws + l*1024, lin_wv + l*256, sc_ws + l*1024, sc_wv + l*256);
        k_msg<<<384, 512, sizeof(SmemT)>>>(l, ei, w3 + l*64*WN, b3 + l*WN);
        k_gate<<<640, 256>>>();
    }
    k_out<<<256, 256>>>(proj, (float*)d_out);
}

// round 13
// speedup vs baseline: 2.7463x; 1.3564x over previous
#include <cuda_runtime.h>
#include <cuda_bf16.h>
#include <math.h>
#include <stdint.h>

#define N_NODES 2048
#define N_EDGES 49152
#define HID     80
#define AGGD    96
#define WN      3328
#define EPB     128

__device__ float g_geo[N_EDGES * 20];
__device__ __nv_bfloat16 g_f2h[4L * N_EDGES * 64];
__device__ __nv_bfloat16 g_f2l[4L * N_EDGES * 64];
__device__ __nv_bfloat16 g_w3h[104L * 8192];
__device__ __nv_bfloat16 g_w3l[104L * 8192];
__device__ float g_b3r[104 * 128];
__device__ float g_h    [N_NODES * HID];
__device__ float g_hx   [N_NODES * HID];
__device__ float g_xself[N_NODES * HID];
__device__ float g_agg  [N_NODES * AGGD];

__device__ __forceinline__ unsigned s2u(const void* p) {
    unsigned a;
    asm("{ .reg .u64 t; cvta.to.shared.u64 t, %1; cvt.u32.u64 %0, t; }" : "=r"(a) : "l"(p));
    return a;
}
__device__ __forceinline__ void ldsm4(uint32_t* r, unsigned addr) {
    asm volatile("ldmatrix.sync.aligned.m8n8.x4.shared.b16 {%0,%1,%2,%3}, [%4];"
                 : "=r"(r[0]), "=r"(r[1]), "=r"(r[2]), "=r"(r[3]) : "r"(addr));
}
__device__ __forceinline__ void mma16816(float* c, const uint32_t* a, uint32_t b0, uint32_t b1) {
    asm volatile("mma.sync.aligned.m16n8k16.row.col.f32.bf16.bf16.f32 "
                 "{%0,%1,%2,%3}, {%4,%5,%6,%7}, {%8,%9}, {%0,%1,%2,%3};"
                 : "+f"(c[0]), "+f"(c[1]), "+f"(c[2]), "+f"(c[3])
                 : "r"(a[0]), "r"(a[1]), "r"(a[2]), "r"(a[3]), "r"(b0), "r"(b1));
}
__device__ __forceinline__ void cpa16(unsigned dst, const void* src) {
    asm volatile("cp.async.ca.shared.global [%0], [%1], 16;" :: "r"(dst), "l"(src) : "memory");
}
#define CPA_COMMIT() asm volatile("cp.async.commit_group;" ::: "memory")
#define CPA_WAIT0()  asm volatile("cp.async.wait_group 0;" ::: "memory")

// ---- chunk tables (26 chunks x 128 slots) ----
__device__ const int cb_[26]  = {0,0,0,0,0,0,0,0,0,0,0,0, 1536,1536,1536,1536,1536,1536,
                                 2304,2304,2304,2304, 2816,2816, 3072,3072};
__device__ const int cw_[26]  = {48,48,48,48,48,48,48,48,48,48,48,48, 48,48,48,48,48,48,
                                 16,16,16,16, 16,16, 16,16};
__device__ const int cnu_[26] = {32,32,32,32,32,32,32,32,32,32,32,32, 16,16,16,16,16,16,
                                 32,32,32,32, 16,16, 16,16};
__device__ const int cwb_[26] = {0,4,8,12,16,20,24,28,32,36,40,44, 0,8,16,24,32,40,
                                 0,4,8,12, 0,8, 0,8};
__device__ const int cbk_[26] = {0,0,0,0,0,0,0,0,0,0,0,0, 1,1,1,1,1,1, 2,2,2,2, 3,3, 4,4};

// ---------------- W3 pre-split into chunk layout ----------------
__global__ __launch_bounds__(256)
void k_prew(const float* __restrict__ W3, const float* __restrict__ B3) {
    int b = blockIdx.x;
    int l = b / 26, c = b - l*26;
    int base = cb_[c], W = cw_[c], nu = cnu_[c], wb = cwb_[c];
    const float* W3c = W3 + (size_t)l*64*WN;
    for (int i = threadIdx.x; i < 8192; i += 256) {
        int s = i >> 6, k = i & 63;
        int u, wo;
        if (nu == 32) { u = s & 31; wo = s >> 5; } else { u = s & 15; wo = s >> 4; }
        float v = W3c[(size_t)k*WN + base + u*W + wb + wo];
        __nv_bfloat16 h = __float2bfloat16(v);
        g_w3h[(size_t)b*8192 + i] = h;
        g_w3l[(size_t)b*8192 + i] = __float2bfloat16(v - __bfloat162float(h));
    }
    if (threadIdx.x < 128) {
        int s = threadIdx.x, u, wo;
        if (nu == 32) { u = s & 31; wo = s >> 5; } else { u = s & 15; wo = s >> 4; }
        g_b3r[b*128 + s] = B3[l*WN + base + u*W + wb + wo];
    }
}

// ---------------- fused geometry + embed-init ----------------
__global__ void kA(const float* __restrict__ pos, const int* __restrict__ ei,
                   const float* __restrict__ x, const float* __restrict__ ew) {
    if (blockIdx.x < 192) {
        int e = blockIdx.x*256 + threadIdx.x;
        int s = ei[e], d = ei[N_EDGES + e];
        float rx = pos[d*3+0]-pos[s*3+0], ry = pos[d*3+1]-pos[s*3+1], rz = pos[d*3+2]-pos[s*3+2];
        float r = fmaxf(sqrtf(rx*rx+ry*ry+rz*rz), 1e-6f);
        float inv = 1.f/r;
        float dx = rx*inv, dy = ry*inv, dz = rz*inv;
        float* g = g_geo + e*20;
        const float s3 = 1.7320508075688772f;
        g[0]=s3*dx; g[1]=s3*dy; g[2]=s3*dz;
        const float c15 = 3.872983346207417f;
        float y20=c15*dx*dy, y21=c15*dy*dz, y22=1.1180339887498949f*(3.f*dz*dz-1.f);
        float y23=c15*dx*dz, y24=0.5f*c15*(dx*dx-dy*dy);
        const float s2=0.7071067811865476f, s6=0.4082482904638631f, q=0.7745966692414834f;
        g[3]=q*(-s6*y22+s2*y24); g[4]=q*(-s6*y22-s2*y24); g[5]=q*(2.f*s6*y22);
        g[6]=q*s2*y20; g[7]=q*s2*y21; g[8]=q*s2*y23;
        float u = r*(1.f/6.f);
        float u3=u*u*u, u6=u3*u3, u7=u6*u, u8=u7*u;
        float fc = (u<1.f) ? (1.f-28.f*u6+48.f*u7-21.f*u8) : 0.f;
        float pref = 0.5773502691896258f*inv*fc;
        float pir = 3.14159265358979323846f*r*(1.f/6.f);
        #pragma unroll
        for (int n = 1; n <= 8; ++n) g[8+n] = pref*sinf((float)n*pir);
    } else {
        int idx = (blockIdx.x-192)*256 + threadIdx.x;
        if (idx >= N_NODES*HID) return;
        int n = idx/HID, c = idx - n*HID;
        float v = 0.f;
        if (c < 32) {
            float a = 0.f;
            #pragma unroll
            for (int u = 0; u < 16; ++u) a = fmaf(x[n*16+u], ew[u*32+c], a);
            v = a*0.25f;
        }
        g_h[idx] = v;
    }
}

// ---------------- radial MLP (all 4 layers), split-bf16 output ----------------
__global__ __launch_bounds__(256)
void k_radial4(const float* __restrict__ W1, const float* __restrict__ B1,
               const float* __restrict__ W2, const float* __restrict__ B2) {
    __shared__ float w1s[512], b1s[64], w2s[4096], b2s[64];
    int tid = threadIdx.x;
    int l = blockIdx.x / 192;
    int e = (blockIdx.x - l*192)*256 + tid;
    const float* W1l = W1 + l*512; const float* W2l = W2 + l*4096;
    for (int i = tid; i < 512;  i += 256) w1s[i]=W1l[i];
    for (int i = tid; i < 4096; i += 256) w2s[i]=W2l[i];
    if (tid < 64) { b1s[tid]=B1[l*64+tid]; b2s[tid]=B2[l*64+tid]; }
    __syncthreads();
    float rbf[8];
    #pragma unroll
    for (int n = 0; n < 8; ++n) rbf[n] = g_geo[e*20+9+n];
    float f1[64];
    #pragma unroll
    for (int o = 0; o < 64; ++o) {
        float a = b1s[o];
        #pragma unroll
        for (int n = 0; n < 8; ++n) a = fmaf(rbf[n], w1s[n*64+o], a);
        f1[o] = a/(1.f+__expf(-a));
    }
    size_t ob = ((size_t)l*N_EDGES + e)*64;
    for (int o = 0; o < 64; ++o) {
        float a = b2s[o];
        #pragma unroll
        for (int k = 0; k < 64; ++k) a = fmaf(f1[k], w2s[k*64+o], a);
        a = a/(1.f+__expf(-a));
        __nv_bfloat16 h = __float2bfloat16(a);
        g_f2h[ob+o] = h;
        g_f2l[ob+o] = __float2bfloat16(a - __bfloat162float(h));
    }
}

// ---------------- node linears + agg zero ----------------
__global__ void k_nodelin(const float* __restrict__ Ws, const float* __restrict__ Wv,
                          const float* __restrict__ Ss, const float* __restrict__ Sv) {
    __shared__ float ws_[1024], wv_[256], ss_[1024], sv_[256];
    int tid = threadIdx.x;
    int gid = blockIdx.x*256 + tid;
    for (int i = gid; i < N_NODES*AGGD; i += 64*256) g_agg[i] = 0.f;
    for (int i = tid; i < 1024; i += 256) { ws_[i]=Ws[i]; ss_[i]=Ss[i]; }
    if (tid < 256) { wv_[tid]=Wv[tid]; sv_[tid]=Sv[tid]; }
    __syncthreads();
    int n = gid >> 3, slot = gid & 7;
    float hs[32], hv[48];
    #pragma unroll
    for (int i = 0; i < 32; ++i) hs[i] = g_h[n*HID+i];
    #pragma unroll
    for (int i = 0; i < 48; ++i) hv[i] = g_h[n*HID+32+i];
    const float is = 0.17677669529663687f, iv = 0.25f;
    #pragma unroll
    for (int c4 = 0; c4 < 4; ++c4) {
        int w = slot*4 + c4;
        float a=0.f, b=0.f;
        #pragma unroll
        for (int u = 0; u < 32; ++u) { a=fmaf(hs[u],ws_[u*32+w],a); b=fmaf(hs[u],ss_[u*32+w],b); }
        g_hx[n*HID+w]=a*is; g_xself[n*HID+w]=b*is;
    }
    #pragma unroll
    for (int c2 = 0; c2 < 2; ++c2) {
        int w = slot*2 + c2;
        float a0=0,a1=0,a2=0,b0=0,b1=0,b2=0;
        #pragma unroll
        for (int u = 0; u < 16; ++u) {
            float wl=wv_[u*16+w], sl=sv_[u*16+w];
            a0=fmaf(hv[u*3+0],wl,a0); a1=fmaf(hv[u*3+1],wl,a1); a2=fmaf(hv[u*3+2],wl,a2);
            b0=fmaf(hv[u*3+0],sl,b0); b1=fmaf(hv[u*3+1],sl,b1); b2=fmaf(hv[u*3+2],sl,b2);
        }
        g_hx[n*HID+32+w*3+0]=a0*iv; g_hx[n*HID+32+w*3+1]=a1*iv; g_hx[n*HID+32+w*3+2]=a2*iv;
        g_xself[n*HID+32+w*3+0]=b0*iv; g_xself[n*HID+32+w*3+1]=b1*iv; g_xself[n*HID+32+w*3+2]=b2*iv;
    }
}

// ---------------- k_msg ----------------
#define RP 72   // bf16 row pitch (144 B)

struct SmemT {
    __nv_bfloat16 Ah[128*RP];
    __nv_bfloat16 Al[128*RP];
    __nv_bfloat16 Bh[2][128*RP];
    __nv_bfloat16 Bl[2][128*RP];
    float bias[2][128];
    float sj[32*EPB];
    float p2[16*EPB];
    float vj[48*EPB];
    float y1[3*EPB];
    float Mq[6*EPB];
    float t3[16*EPB];
    float accs[48*EPB];
    float accv[48*EPB];
    int srcs[EPB];
    int dsts[EPB];
};

__global__ __launch_bounds__(512, 1)
void k_msg(int l, const int* __restrict__ ei) {
    extern __shared__ unsigned char smraw[];
    SmemT* sm = (SmemT*)smraw;
    int tid = threadIdx.x;
    int wid = tid >> 5, lid = tid & 31;
    int e0 = blockIdx.x * EPB;
    int l26 = l * 26;

    if (tid < EPB) { sm->srcs[tid] = ei[e0+tid]; sm->dsts[tid] = ei[N_EDGES+e0+tid]; }

    // A tiles via cp.async
    {
        unsigned ahU = s2u(sm->Ah), alU = s2u(sm->Al);
        const char* sh = (const char*)(g_f2h + ((size_t)l*N_EDGES + e0)*64);
        const char* sl = (const char*)(g_f2l + ((size_t)l*N_EDGES + e0)*64);
        for (int t = tid; t < 1024; t += 512) {
            int r = t >> 3, k8 = t & 7;
            unsigned d = (unsigned)(r*144 + k8*16);
            cpa16(ahU + d, sh + r*128 + k8*16);
            cpa16(alU + d, sl + r*128 + k8*16);
        }
    }
    // B chunk 0
    auto issueB = [&](int c) {
        unsigned bh = s2u(sm->Bh[c & 1]), bl = s2u(sm->Bl[c & 1]);
        const char* srch = (const char*)(g_w3h + (size_t)(l26 + c)*8192);
        const char* srcl = (const char*)(g_w3l + (size_t)(l26 + c)*8192);
        for (int t = tid; t < 1024; t += 512) {
            int s = t >> 3, k8 = t & 7;
            unsigned d = (unsigned)(s*144 + k8*16);
            cpa16(bh + d, srch + s*128 + k8*16);
            cpa16(bl + d, srcl + s*128 + k8*16);
        }
        if (tid < 32) cpa16(s2u(&sm->bias[c & 1][0]) + tid*16,
                            (const char*)(g_b3r + (size_t)(l26 + c)*128) + tid*16);
        CPA_COMMIT();
    };
    issueB(0);
    __syncthreads();   // srcs visible

    for (int i = tid; i < EPB*80; i += 512) {
        int ee = i/80, c = i - ee*80;
        float v = g_hx[sm->srcs[ee]*HID + c];
        if (c < 32) sm->sj[c*EPB+ee] = v; else sm->vj[(c-32)*EPB+ee] = v;
    }
    for (int i = tid; i < EPB*9; i += 512) {
        int ee = i/9, c = i - ee*9;
        float v = g_geo[(e0+ee)*20 + c];
        if (c < 3) sm->y1[c*EPB+ee] = v; else sm->Mq[(c-3)*EPB+ee] = v;
    }
    __syncthreads();
    for (int i = tid; i < EPB*16; i += 512) {
        int ee = i & 127, u = i >> 7;
        float v0 = sm->vj[(u*3+0)*EPB+ee], v1 = sm->vj[(u*3+1)*EPB+ee], v2 = sm->vj[(u*3+2)*EPB+ee];
        sm->p2[u*EPB+ee] = (v0*sm->y1[ee] + v1*sm->y1[EPB+ee] + v2*sm->y1[2*EPB+ee])
                           * 0.5773502691896258f;
    }

    int wq = wid >> 2;
    int rgrp = (wid & 3) * 32;
    int cg = wq * 32;
    int q = lid >> 2, ln4 = lid & 3;
    unsigned ahB = s2u(sm->Ah), alB = s2u(sm->Al);
    unsigned a_off = (unsigned)((rgrp + (lid & 15))*144 + ((lid >> 4)*8)*2);
    unsigned b_off = (unsigned)((cg + ((lid >> 4)*8) + (lid & 7))*144 + (((lid >> 3) & 1)*8)*2);

    for (int c = 0; c < 26; ++c) {
        int wb = cwb_[c], bk = cbk_[c];
        CPA_WAIT0();
        __syncthreads();
        if (c < 25) issueB(c + 1);

        unsigned bhB = s2u(sm->Bh[c & 1]), blB = s2u(sm->Bl[c & 1]);
        const float* biasc = sm->bias[c & 1];

        float acc[2][4][4];
        #pragma unroll
        for (int i = 0; i < 2; ++i)
            #pragma unroll
            for (int j = 0; j < 4; ++j)
                #pragma unroll
                for (int k = 0; k < 4; ++k) acc[i][j][k] = 0.f;
        #pragma unroll
        for (int k0 = 0; k0 < 64; k0 += 16) {
            uint32_t Ah0[4],Ah1[4],Al0[4],Al1[4],Bh0[4],Bh1[4],Bl0[4],Bl1[4];
            ldsm4(Ah0, ahB + a_off + k0*2);
            ldsm4(Ah1, ahB + a_off + 16*144 + k0*2);
            ldsm4(Al0, alB + a_off + k0*2);
            ldsm4(Al1, alB + a_off + 16*144 + k0*2);
            ldsm4(Bh0, bhB + b_off + k0*2);
            ldsm4(Bh1, bhB + b_off + 16*144 + k0*2);
            ldsm4(Bl0, blB + b_off + k0*2);
            ldsm4(Bl1, blB + b_off + 16*144 + k0*2);
            uint32_t* Bhp[4] = {Bh0, Bh0+2, Bh1, Bh1+2};
            uint32_t* Blp[4] = {Bl0, Bl0+2, Bl1, Bl1+2};
            #pragma unroll
            for (int nt = 0; nt < 4; ++nt) {
                mma16816(acc[0][nt], Ah0, Bhp[nt][0], Bhp[nt][1]);
                mma16816(acc[1][nt], Ah1, Bhp[nt][0], Bhp[nt][1]);
                mma16816(acc[0][nt], Ah0, Blp[nt][0], Blp[nt][1]);
                mma16816(acc[1][nt], Ah1, Blp[nt][0], Blp[nt][1]);
                mma16816(acc[0][nt], Al0, Bhp[nt][0], Bhp[nt][1]);
                mma16816(acc[1][nt], Al1, Bhp[nt][0], Bhp[nt][1]);
            }
        }

        float bias8[8];
        #pragma unroll
        for (int nt = 0; nt < 4; ++nt)
            #pragma unroll
            for (int jj = 0; jj < 2; ++jj)
                bias8[nt*2+jj] = biasc[cg + nt*8 + ln4*2 + jj];

        if (bk == 0 || bk == 2) {
            #pragma unroll
            for (int i = 0; i < 4; ++i) {
                int er = rgrp + q + i*8;
                float p = 0.f;
                #pragma unroll
                for (int nt = 0; nt < 4; ++nt)
                    #pragma unroll
                    for (int jj = 0; jj < 2; ++jj) {
                        int u = nt*8 + ln4*2 + jj;
                        p = fmaf(acc[i>>1][nt][(i&1)*2+jj] + bias8[nt*2+jj],
                                 sm->sj[u*EPB+er], p);
                    }
                p += __shfl_xor_sync(0xFFFFFFFFu, p, 1);
                p += __shfl_xor_sync(0xFFFFFFFFu, p, 2);
                if (ln4 == 0) {
                    if (bk == 0) sm->accs[(wb+wq)*EPB+er] = p;
                    else         sm->t3[(wb+wq)*EPB+er]   = p;
                }
            }
        } else if (bk == 1) {
            #pragma unroll
            for (int i = 0; i < 4; ++i) {
                int er = rgrp + q + i*8;
                #pragma unroll
                for (int h = 0; h < 2; ++h) {
                    float p = 0.f;
                    #pragma unroll
                    for (int n2 = 0; n2 < 2; ++n2) {
                        int nt = h*2 + n2;
                        #pragma unroll
                        for (int jj = 0; jj < 2; ++jj) {
                            int u = n2*8 + ln4*2 + jj;
                            p = fmaf(acc[i>>1][nt][(i&1)*2+jj] + bias8[nt*2+jj],
                                     sm->p2[u*EPB+er], p);
                        }
                    }
                    p += __shfl_xor_sync(0xFFFFFFFFu, p, 1);
                    p += __shfl_xor_sync(0xFFFFFFFFu, p, 2);
                    if (ln4 == 0) sm->accs[(wb + wq*2 + h)*EPB+er] += p;
                }
            }
        } else {
            #pragma unroll
            for (int i = 0; i < 4; ++i) {
                int er = rgrp + q + i*8;
                float M00=0,M11=0,M22=0,M01=0,M12=0,M02=0;
                if (bk == 4) {
                    M00=sm->Mq[er]; M11=sm->Mq[EPB+er]; M22=sm->Mq[2*EPB+er];
                    M01=sm->Mq[3*EPB+er]; M12=sm->Mq[4*EPB+er]; M02=sm->Mq[5*EPB+er];
                }
                #pragma unroll
                for (int h = 0; h < 2; ++h) {
                    float a0=0.f, a1=0.f, a2=0.f;
                    #pragma unroll
                    for (int n2 = 0; n2 < 2; ++n2) {
                        int nt = h*2 + n2;
                        #pragma unroll
                        for (int jj = 0; jj < 2; ++jj) {
                            int u = n2*8 + ln4*2 + jj;
                            float bv = acc[i>>1][nt][(i&1)*2+jj] + bias8[nt*2+jj];
                            float v0 = sm->vj[(u*3+0)*EPB+er];
                            float v1 = sm->vj[(u*3+1)*EPB+er];
                            float v2 = sm->vj[(u*3+2)*EPB+er];
                            float f0, f1, f2;
                            if (bk == 4) {
                                f0 = v0*M00 + v1*M01 + v2*M02;
                                f1 = v0*M01 + v1*M11 + v2*M12;
                                f2 = v0*M02 + v1*M12 + v2*M22;
                            } else { f0 = v0; f1 = v1; f2 = v2; }
                            a0 = fmaf(bv, f0, a0);
                            a1 = fmaf(bv, f1, a1);
                            a2 = fmaf(bv, f2, a2);
                        }
                    }
                    a0 += __shfl_xor_sync(0xFFFFFFFFu, a0, 1);
                    a0 += __shfl_xor_sync(0xFFFFFFFFu, a0, 2);
                    a1 += __shfl_xor_sync(0xFFFFFFFFu, a1, 1);
                    a1 += __shfl_xor_sync(0xFFFFFFFFu, a1, 2);
                    a2 += __shfl_xor_sync(0xFFFFFFFFu, a2, 1);
                    a2 += __shfl_xor_sync(0xFFFFFFFFu, a2, 2);
                    if (ln4 == 0) {
                        int w = wb + wq*2 + h;
                        if (bk == 3) {
                            sm->accv[(w*3+0)*EPB+er] = a0;
                            sm->accv[(w*3+1)*EPB+er] = a1;
                            sm->accv[(w*3+2)*EPB+er] = a2;
                        } else {
                            sm->accv[(w*3+0)*EPB+er] += a0;
                            sm->accv[(w*3+1)*EPB+er] += a1;
                            sm->accv[(w*3+2)*EPB+er] += a2;
                        }
                    }
                }
            }
        }
    }
    __syncthreads();

    const float SS = 0.029462782549439483f;  // 1/sqrt(48*24)
    const float SV = 0.025515518153991442f;  // 1/sqrt(64*24)
    int e = tid & 127, wp = tid >> 7;
    int dd = sm->dsts[e];
    for (int c = wp*24; c < wp*24+24; ++c) {
        float val;
        if (c < 48) val = sm->accs[c*EPB+e]*SS;
        else {
            int cc = c-48, w = cc/3, i = cc-w*3;
            val = (sm->accv[cc*EPB+e] + sm->y1[i*EPB+e]*sm->t3[w*EPB+e])*SV;
        }
        atomicAdd(&g_agg[dd*AGGD+c], val);
    }
}

__global__ void k_gate() {
    int idx = blockIdx.x*blockDim.x + threadIdx.x;
    if (idx >= N_NODES*HID) return;
    int n = idx/HID, c = idx - n*HID;
    float add;
    if (c < 32) {
        float a = g_agg[n*AGGD+c];
        add = a/(1.f+expf(-a));
    } else {
        int cc = c-32, w = cc/3;
        float gg = g_agg[n*AGGD+32+w];
        add = g_agg[n*AGGD+48+cc]/(1.f+expf(-gg));
    }
    g_h[idx] = g_h[idx] + g_xself[idx] + add;
}

__global__ void k_out(const float* __restrict__ proj, float* __restrict__ out) {
    int idx = blockIdx.x*blockDim.x + threadIdx.x;
    if (idx >= N_NODES*32) return;
    int n = idx >> 5, j = idx & 31;
    float a = 0.f;
    #pragma unroll
    for (int u = 0; u < 32; ++u) a = fmaf(g_h[n*HID+u], proj[u*32+j], a);
    out[idx] = a*0.17677669529663687f;
}

extern "C" void kernel_launch(void* const* d_in, const int* in_sizes, int n_in,
                              void* d_out, int out_size) {
    const float* x      = (const float*)d_in[0];
    const float* pos    = (const float*)d_in[1];
    const int*   ei     = (const int*)  d_in[2];
    const float* embed  = (const float*)d_in[3];
    const float* proj   = (const float*)d_in[4];
    const float* lin_ws = (const float*)d_in[5];
    const float* lin_wv = (const float*)d_in[6];
    const float* sc_ws  = (const float*)d_in[7];
    const float* sc_wv  = (const float*)d_in[8];
    const float* w1     = (const float*)d_in[9];
    const float* b1     = (const float*)d_in[10];
    const float* w2     = (const float*)d_in[11];
    const float* b2     = (const float*)d_in[12];
    const float* w3     = (const float*)d_in[13];
    const float* b3     = (const float*)d_in[14];

    cudaFuncSetAttribute(k_msg, cudaFuncAttributeMaxDynamicSharedMemorySize, (int)sizeof(SmemT));

    kA<<<832, 256>>>(pos, ei, x, embed);
    k_prew<<<104, 256>>>(w3, b3);
    k_radial4<<<768, 256>>>(w1, b1, w2, b2);
    for (int l = 0; l < 4; ++l) {
        k_nodelin<<<64, 256>>>(lin_ws + l*1024, lin_wv + l*256, sc_ws + l*1024, sc_wv + l*256);
        k_msg<<<384, 512, sizeof(SmemT)>>>(l, ei);
        k_gate<<<640, 256>>>();
    }
    k_out<<<256, 256>>>(proj, (float*)d_out);
}

// round 14
// speedup vs baseline: 3.1832x; 1.1591x over previous
#include <cuda_runtime.h>
#include <cuda_bf16.h>
#include <math.h>
#include <stdint.h>

#define N_NODES 2048
#define N_EDGES 49152
#define HID     80
#define AGGD    96
#define WN      3328
#define EPB     128

__device__ float g_geo[N_EDGES * 20];
__device__ __nv_bfloat16 g_f2h[4L * N_EDGES * 64];
__device__ __nv_bfloat16 g_w3h[104L * 8192];
__device__ __nv_bfloat16 g_w3l[104L * 8192];
__device__ float g_b3r[104 * 128];
__device__ float g_h    [N_NODES * HID];
__device__ float g_hx   [N_NODES * HID];
__device__ float g_xself[N_NODES * HID];
__device__ float g_agg  [N_NODES * AGGD];

__device__ __forceinline__ unsigned s2u(const void* p) {
    unsigned a;
    asm("{ .reg .u64 t; cvta.to.shared.u64 t, %1; cvt.u32.u64 %0, t; }" : "=r"(a) : "l"(p));
    return a;
}
__device__ __forceinline__ void ldsm4(uint32_t* r, unsigned addr) {
    asm volatile("ldmatrix.sync.aligned.m8n8.x4.shared.b16 {%0,%1,%2,%3}, [%4];"
                 : "=r"(r[0]), "=r"(r[1]), "=r"(r[2]), "=r"(r[3]) : "r"(addr));
}
__device__ __forceinline__ void mma16816(float* c, const uint32_t* a, uint32_t b0, uint32_t b1) {
    asm volatile("mma.sync.aligned.m16n8k16.row.col.f32.bf16.bf16.f32 "
                 "{%0,%1,%2,%3}, {%4,%5,%6,%7}, {%8,%9}, {%0,%1,%2,%3};"
                 : "+f"(c[0]), "+f"(c[1]), "+f"(c[2]), "+f"(c[3])
                 : "r"(a[0]), "r"(a[1]), "r"(a[2]), "r"(a[3]), "r"(b0), "r"(b1));
}
__device__ __forceinline__ void cpa16(unsigned dst, const void* src) {
    asm volatile("cp.async.ca.shared.global [%0], [%1], 16;" :: "r"(dst), "l"(src) : "memory");
}
#define CPA_COMMIT() asm volatile("cp.async.commit_group;" ::: "memory")
#define CPA_WAIT0()  asm volatile("cp.async.wait_group 0;" ::: "memory")

// ---- chunk tables (26 chunks x 128 slots) ----
__device__ const int cb_[26]  = {0,0,0,0,0,0,0,0,0,0,0,0, 1536,1536,1536,1536,1536,1536,
                                 2304,2304,2304,2304, 2816,2816, 3072,3072};
__device__ const int cw_[26]  = {48,48,48,48,48,48,48,48,48,48,48,48, 48,48,48,48,48,48,
                                 16,16,16,16, 16,16, 16,16};
__device__ const int cnu_[26] = {32,32,32,32,32,32,32,32,32,32,32,32, 16,16,16,16,16,16,
                                 32,32,32,32, 16,16, 16,16};
__device__ const int cwb_[26] = {0,4,8,12,16,20,24,28,32,36,40,44, 0,8,16,24,32,40,
                                 0,4,8,12, 0,8, 0,8};
__device__ const int cbk_[26] = {0,0,0,0,0,0,0,0,0,0,0,0, 1,1,1,1,1,1, 2,2,2,2, 3,3, 4,4};

// ---------------- kA: geometry + embed-init + W3 pre-split ----------------
__global__ void kA(const float* __restrict__ pos, const int* __restrict__ ei,
                   const float* __restrict__ x, const float* __restrict__ ew,
                   const float* __restrict__ W3, const float* __restrict__ B3) {
    if (blockIdx.x < 192) {
        int e = blockIdx.x*256 + threadIdx.x;
        int s = ei[e], d = ei[N_EDGES + e];
        float rx = pos[d*3+0]-pos[s*3+0], ry = pos[d*3+1]-pos[s*3+1], rz = pos[d*3+2]-pos[s*3+2];
        float r = fmaxf(sqrtf(rx*rx+ry*ry+rz*rz), 1e-6f);
        float inv = 1.f/r;
        float dx = rx*inv, dy = ry*inv, dz = rz*inv;
        float* g = g_geo + e*20;
        const float s3 = 1.7320508075688772f;
        g[0]=s3*dx; g[1]=s3*dy; g[2]=s3*dz;
        const float c15 = 3.872983346207417f;
        float y20=c15*dx*dy, y21=c15*dy*dz, y22=1.1180339887498949f*(3.f*dz*dz-1.f);
        float y23=c15*dx*dz, y24=0.5f*c15*(dx*dx-dy*dy);
        const float s2=0.7071067811865476f, s6=0.4082482904638631f, q=0.7745966692414834f;
        g[3]=q*(-s6*y22+s2*y24); g[4]=q*(-s6*y22-s2*y24); g[5]=q*(2.f*s6*y22);
        g[6]=q*s2*y20; g[7]=q*s2*y21; g[8]=q*s2*y23;
        float u = r*(1.f/6.f);
        float u3=u*u*u, u6=u3*u3, u7=u6*u, u8=u7*u;
        float fc = (u<1.f) ? (1.f-28.f*u6+48.f*u7-21.f*u8) : 0.f;
        float pref = 0.5773502691896258f*inv*fc;
        float pir = 3.14159265358979323846f*r*(1.f/6.f);
        #pragma unroll
        for (int n = 1; n <= 8; ++n) g[8+n] = pref*sinf((float)n*pir);
    } else if (blockIdx.x < 832) {
        int idx = (blockIdx.x-192)*256 + threadIdx.x;
        if (idx >= N_NODES*HID) return;
        int n = idx/HID, c = idx - n*HID;
        float v = 0.f;
        if (c < 32) {
            float a = 0.f;
            #pragma unroll
            for (int u = 0; u < 16; ++u) a = fmaf(x[n*16+u], ew[u*32+c], a);
            v = a*0.25f;
        }
        g_h[idx] = v;
    } else {
        int b = blockIdx.x - 832;            // 0..103
        int l = b / 26, c = b - l*26;
        int base = cb_[c], W = cw_[c], nu = cnu_[c], wb = cwb_[c];
        const float* W3c = W3 + (size_t)l*64*WN;
        for (int i = threadIdx.x; i < 8192; i += 256) {
            int s = i >> 6, k = i & 63;
            int u, wo;
            if (nu == 32) { u = s & 31; wo = s >> 5; } else { u = s & 15; wo = s >> 4; }
            float v = W3c[(size_t)k*WN + base + u*W + wb + wo];
            __nv_bfloat16 h = __float2bfloat16(v);
            g_w3h[(size_t)b*8192 + i] = h;
            g_w3l[(size_t)b*8192 + i] = __float2bfloat16(v - __bfloat162float(h));
        }
        if (threadIdx.x < 128) {
            int s = threadIdx.x, u, wo;
            if (nu == 32) { u = s & 31; wo = s >> 5; } else { u = s & 15; wo = s >> 4; }
            g_b3r[b*128 + s] = B3[l*WN + base + u*W + wb + wo];
        }
    }
}

// ---------------- radial MLP (all 4 layers), bf16 output ----------------
__global__ __launch_bounds__(256)
void k_radial4(const float* __restrict__ W1, const float* __restrict__ B1,
               const float* __restrict__ W2, const float* __restrict__ B2) {
    __shared__ float w1s[512], b1s[64], w2s[4096], b2s[64];
    int tid = threadIdx.x;
    int l = blockIdx.x / 192;
    int e = (blockIdx.x - l*192)*256 + tid;
    const float* W1l = W1 + l*512; const float* W2l = W2 + l*4096;
    for (int i = tid; i < 512;  i += 256) w1s[i]=W1l[i];
    for (int i = tid; i < 4096; i += 256) w2s[i]=W2l[i];
    if (tid < 64) { b1s[tid]=B1[l*64+tid]; b2s[tid]=B2[l*64+tid]; }
    __syncthreads();
    float rbf[8];
    #pragma unroll
    for (int n = 0; n < 8; ++n) rbf[n] = g_geo[e*20+9+n];
    float f1[64];
    #pragma unroll
    for (int o = 0; o < 64; ++o) {
        float a = b1s[o];
        #pragma unroll
        for (int n = 0; n < 8; ++n) a = fmaf(rbf[n], w1s[n*64+o], a);
        f1[o] = a/(1.f+__expf(-a));
    }
    size_t ob = ((size_t)l*N_EDGES + e)*64;
    for (int o = 0; o < 64; ++o) {
        float a = b2s[o];
        #pragma unroll
        for (int k = 0; k < 64; ++k) a = fmaf(f1[k], w2s[k*64+o], a);
        a = a/(1.f+__expf(-a));
        g_f2h[ob+o] = __float2bfloat16(a);
    }
}

// ---------------- fused gate(prev layer) + node linears + agg zero ----------------
__global__ __launch_bounds__(256)
void k_fuse(int do_gate, const float* __restrict__ Ws, const float* __restrict__ Wv,
            const float* __restrict__ Ss, const float* __restrict__ Sv) {
    __shared__ float ws_[1024], wv_[256], ss_[1024], sv_[256];
    int tid = threadIdx.x;
    int gid = blockIdx.x*256 + tid;
    int n = gid >> 3, slot = gid & 7;
    for (int i = tid; i < 1024; i += 256) { ws_[i]=Ws[i]; ss_[i]=Ss[i]; }
    if (tid < 256) { wv_[tid]=Wv[tid]; sv_[tid]=Sv[tid]; }
    if (do_gate) {
        #pragma unroll
        for (int cc = 0; cc < 10; ++cc) {
            int c = slot*10 + cc;
            float add;
            if (c < 32) {
                float a = g_agg[n*AGGD+c];
                add = a/(1.f+__expf(-a));
            } else {
                int c2 = c-32, w = c2/3;
                float gg = g_agg[n*AGGD+32+w];
                add = g_agg[n*AGGD+48+c2]/(1.f+__expf(-gg));
            }
            g_h[n*HID+c] = g_h[n*HID+c] + g_xself[n*HID+c] + add;
        }
    }
    __syncthreads();
    // zero agg for this block's nodes (next accumulation round)
    for (int i = tid; i < 32*AGGD; i += 256) g_agg[(size_t)blockIdx.x*32*AGGD + i] = 0.f;

    float hs[32], hv[48];
    #pragma unroll
    for (int i = 0; i < 32; ++i) hs[i] = g_h[n*HID+i];
    #pragma unroll
    for (int i = 0; i < 48; ++i) hv[i] = g_h[n*HID+32+i];
    const float is = 0.17677669529663687f, iv = 0.25f;
    #pragma unroll
    for (int c4 = 0; c4 < 4; ++c4) {
        int w = slot*4 + c4;
        float a=0.f, b=0.f;
        #pragma unroll
        for (int u = 0; u < 32; ++u) { a=fmaf(hs[u],ws_[u*32+w],a); b=fmaf(hs[u],ss_[u*32+w],b); }
        g_hx[n*HID+w]=a*is; g_xself[n*HID+w]=b*is;
    }
    #pragma unroll
    for (int c2 = 0; c2 < 2; ++c2) {
        int w = slot*2 + c2;
        float a0=0,a1=0,a2=0,b0=0,b1=0,b2=0;
        #pragma unroll
        for (int u = 0; u < 16; ++u) {
            float wl=wv_[u*16+w], sl=sv_[u*16+w];
            a0=fmaf(hv[u*3+0],wl,a0); a1=fmaf(hv[u*3+1],wl,a1); a2=fmaf(hv[u*3+2],wl,a2);
            b0=fmaf(hv[u*3+0],sl,b0); b1=fmaf(hv[u*3+1],sl,b1); b2=fmaf(hv[u*3+2],sl,b2);
        }
        g_hx[n*HID+32+w*3+0]=a0*iv; g_hx[n*HID+32+w*3+1]=a1*iv; g_hx[n*HID+32+w*3+2]=a2*iv;
        g_xself[n*HID+32+w*3+0]=b0*iv; g_xself[n*HID+32+w*3+1]=b1*iv; g_xself[n*HID+32+w*3+2]=b2*iv;
    }
}

// ---------------- k_msg ----------------
#define RP 72   // bf16 row pitch (144 B)

struct SmemT {
    __nv_bfloat16 Ah[128*RP];
    __nv_bfloat16 Bh[2][128*RP];
    __nv_bfloat16 Bl[2][128*RP];
    float bias[2][128];
    float sj[32*EPB];
    float p2[16*EPB];
    float vj[48*EPB];
    float y1[3*EPB];
    float Mq[6*EPB];
    float t3[16*EPB];
    float accs[48*EPB];
    float accv[48*EPB];
    int srcs[EPB];
    int dsts[EPB];
};

__global__ __launch_bounds__(512, 1)
void k_msg(int l, const int* __restrict__ ei) {
    extern __shared__ unsigned char smraw[];
    SmemT* sm = (SmemT*)smraw;
    int tid = threadIdx.x;
    int wid = tid >> 5, lid = tid & 31;
    int e0 = blockIdx.x * EPB;
    int l26 = l * 26;

    if (tid < EPB) { sm->srcs[tid] = ei[e0+tid]; sm->dsts[tid] = ei[N_EDGES+e0+tid]; }

    // A tile via cp.async (hi only)
    {
        unsigned ahU = s2u(sm->Ah);
        const char* sh = (const char*)(g_f2h + ((size_t)l*N_EDGES + e0)*64);
        for (int t = tid; t < 1024; t += 512) {
            int r = t >> 3, k8 = t & 7;
            cpa16(ahU + (unsigned)(r*144 + k8*16), sh + r*128 + k8*16);
        }
    }
    auto issueB = [&](int c) {
        unsigned bh = s2u(sm->Bh[c & 1]), bl = s2u(sm->Bl[c & 1]);
        const char* srch = (const char*)(g_w3h + (size_t)(l26 + c)*8192);
        const char* srcl = (const char*)(g_w3l + (size_t)(l26 + c)*8192);
        for (int t = tid; t < 1024; t += 512) {
            int s = t >> 3, k8 = t & 7;
            unsigned d = (unsigned)(s*144 + k8*16);
            cpa16(bh + d, srch + s*128 + k8*16);
            cpa16(bl + d, srcl + s*128 + k8*16);
        }
        if (tid < 32) cpa16(s2u(&sm->bias[c & 1][0]) + tid*16,
                            (const char*)(g_b3r + (size_t)(l26 + c)*128) + tid*16);
        CPA_COMMIT();
    };
    issueB(0);
    __syncthreads();   // srcs visible

    for (int i = tid; i < EPB*80; i += 512) {
        int ee = i/80, c = i - ee*80;
        float v = g_hx[sm->srcs[ee]*HID + c];
        if (c < 32) sm->sj[c*EPB+ee] = v; else sm->vj[(c-32)*EPB+ee] = v;
    }
    for (int i = tid; i < EPB*9; i += 512) {
        int ee = i/9, c = i - ee*9;
        float v = g_geo[(e0+ee)*20 + c];
        if (c < 3) sm->y1[c*EPB+ee] = v; else sm->Mq[(c-3)*EPB+ee] = v;
    }
    __syncthreads();
    for (int i = tid; i < EPB*16; i += 512) {
        int ee = i & 127, u = i >> 7;
        float v0 = sm->vj[(u*3+0)*EPB+ee], v1 = sm->vj[(u*3+1)*EPB+ee], v2 = sm->vj[(u*3+2)*EPB+ee];
        sm->p2[u*EPB+ee] = (v0*sm->y1[ee] + v1*sm->y1[EPB+ee] + v2*sm->y1[2*EPB+ee])
                           * 0.5773502691896258f;
    }

    int wq = wid >> 2;
    int rgrp = (wid & 3) * 32;
    int cg = wq * 32;
    int q = lid >> 2, ln4 = lid & 3;
    unsigned ahB = s2u(sm->Ah);
    unsigned a_off = (unsigned)((rgrp + (lid & 15))*144 + ((lid >> 4)*8)*2);
    unsigned b_off = (unsigned)((cg + ((lid >> 4)*8) + (lid & 7))*144 + (((lid >> 3) & 1)*8)*2);

    for (int c = 0; c < 26; ++c) {
        int wb = cwb_[c], bk = cbk_[c];
        CPA_WAIT0();
        __syncthreads();
        if (c < 25) issueB(c + 1);

        unsigned bhB = s2u(sm->Bh[c & 1]), blB = s2u(sm->Bl[c & 1]);
        const float* biasc = sm->bias[c & 1];

        float acc[2][4][4];
        #pragma unroll
        for (int i = 0; i < 2; ++i)
            #pragma unroll
            for (int j = 0; j < 4; ++j)
                #pragma unroll
                for (int k = 0; k < 4; ++k) acc[i][j][k] = 0.f;
        #pragma unroll
        for (int k0 = 0; k0 < 64; k0 += 16) {
            uint32_t Ah0[4],Ah1[4],Bh0[4],Bh1[4],Bl0[4],Bl1[4];
            ldsm4(Ah0, ahB + a_off + k0*2);
            ldsm4(Ah1, ahB + a_off + 16*144 + k0*2);
            ldsm4(Bh0, bhB + b_off + k0*2);
            ldsm4(Bh1, bhB + b_off + 16*144 + k0*2);
            ldsm4(Bl0, blB + b_off + k0*2);
            ldsm4(Bl1, blB + b_off + 16*144 + k0*2);
            uint32_t* Bhp[4] = {Bh0, Bh0+2, Bh1, Bh1+2};
            uint32_t* Blp[4] = {Bl0, Bl0+2, Bl1, Bl1+2};
            #pragma unroll
            for (int nt = 0; nt < 4; ++nt) {
                mma16816(acc[0][nt], Ah0, Bhp[nt][0], Bhp[nt][1]);
                mma16816(acc[1][nt], Ah1, Bhp[nt][0], Bhp[nt][1]);
                mma16816(acc[0][nt], Ah0, Blp[nt][0], Blp[nt][1]);
                mma16816(acc[1][nt], Ah1, Blp[nt][0], Blp[nt][1]);
            }
        }

        float bias8[8];
        #pragma unroll
        for (int nt = 0; nt < 4; ++nt)
            #pragma unroll
            for (int jj = 0; jj < 2; ++jj)
                bias8[nt*2+jj] = biasc[cg + nt*8 + ln4*2 + jj];

        if (bk == 0 || bk == 2) {
            #pragma unroll
            for (int i = 0; i < 4; ++i) {
                int er = rgrp + q + i*8;
                float p = 0.f;
                #pragma unroll
                for (int nt = 0; nt < 4; ++nt)
                    #pragma unroll
                    for (int jj = 0; jj < 2; ++jj) {
                        int u = nt*8 + ln4*2 + jj;
                        p = fmaf(acc[i>>1][nt][(i&1)*2+jj] + bias8[nt*2+jj],
                                 sm->sj[u*EPB+er], p);
                    }
                p += __shfl_xor_sync(0xFFFFFFFFu, p, 1);
                p += __shfl_xor_sync(0xFFFFFFFFu, p, 2);
                if (ln4 == 0) {
                    if (bk == 0) sm->accs[(wb+wq)*EPB+er] = p;
                    else         sm->t3[(wb+wq)*EPB+er]   = p;
                }
            }
        } else if (bk == 1) {
            #pragma unroll
            for (int i = 0; i < 4; ++i) {
                int er = rgrp + q + i*8;
                #pragma unroll
                for (int h = 0; h < 2; ++h) {
                    float p = 0.f;
                    #pragma unroll
                    for (int n2 = 0; n2 < 2; ++n2) {
                        int nt = h*2 + n2;
                        #pragma unroll
                        for (int jj = 0; jj < 2; ++jj) {
                            int u = n2*8 + ln4*2 + jj;
                            p = fmaf(acc[i>>1][nt][(i&1)*2+jj] + bias8[nt*2+jj],
                                     sm->p2[u*EPB+er], p);
                        }
                    }
                    p += __shfl_xor_sync(0xFFFFFFFFu, p, 1);
                    p += __shfl_xor_sync(0xFFFFFFFFu, p, 2);
                    if (ln4 == 0) sm->accs[(wb + wq*2 + h)*EPB+er] += p;
                }
            }
        } else {
            #pragma unroll
            for (int i = 0; i < 4; ++i) {
                int er = rgrp + q + i*8;
                float M00=0,M11=0,M22=0,M01=0,M12=0,M02=0;
                if (bk == 4) {
                    M00=sm->Mq[er]; M11=sm->Mq[EPB+er]; M22=sm->Mq[2*EPB+er];
                    M01=sm->Mq[3*EPB+er]; M12=sm->Mq[4*EPB+er]; M02=sm->Mq[5*EPB+er];
                }
                #pragma unroll
                for (int h = 0; h < 2; ++h) {
                    float a0=0.f, a1=0.f, a2=0.f;
                    #pragma unroll
                    for (int n2 = 0; n2 < 2; ++n2) {
                        int nt = h*2 + n2;
                        #pragma unroll
                        for (int jj = 0; jj < 2; ++jj) {
                            int u = n2*8 + ln4*2 + jj;
                            float bv = acc[i>>1][nt][(i&1)*2+jj] + bias8[nt*2+jj];
                            float v0 = sm->vj[(u*3+0)*EPB+er];
                            float v1 = sm->vj[(u*3+1)*EPB+er];
                            float v2 = sm->vj[(u*3+2)*EPB+er];
                            float f0, f1, f2;
                            if (bk == 4) {
                                f0 = v0*M00 + v1*M01 + v2*M02;
                                f1 = v0*M01 + v1*M11 + v2*M12;
                                f2 = v0*M02 + v1*M12 + v2*M22;
                            } else { f0 = v0; f1 = v1; f2 = v2; }
                            a0 = fmaf(bv, f0, a0);
                            a1 = fmaf(bv, f1, a1);
                            a2 = fmaf(bv, f2, a2);
                        }
                    }
                    a0 += __shfl_xor_sync(0xFFFFFFFFu, a0, 1);
                    a0 += __shfl_xor_sync(0xFFFFFFFFu, a0, 2);
                    a1 += __shfl_xor_sync(0xFFFFFFFFu, a1, 1);
                    a1 += __shfl_xor_sync(0xFFFFFFFFu, a1, 2);
                    a2 += __shfl_xor_sync(0xFFFFFFFFu, a2, 1);
                    a2 += __shfl_xor_sync(0xFFFFFFFFu, a2, 2);
                    if (ln4 == 0) {
                        int w = wb + wq*2 + h;
                        if (bk == 3) {
                            sm->accv[(w*3+0)*EPB+er] = a0;
                            sm->accv[(w*3+1)*EPB+er] = a1;
                            sm->accv[(w*3+2)*EPB+er] = a2;
                        } else {
                            sm->accv[(w*3+0)*EPB+er] += a0;
                            sm->accv[(w*3+1)*EPB+er] += a1;
                            sm->accv[(w*3+2)*EPB+er] += a2;
                        }
                    }
                }
            }
        }
    }
    __syncthreads();

    const float SS = 0.029462782549439483f;  // 1/sqrt(48*24)
    const float SV = 0.025515518153991442f;  // 1/sqrt(64*24)
    int e = tid & 127, wp = tid >> 7;
    int dd = sm->dsts[e];
    for (int c = wp*24; c < wp*24+24; ++c) {
        float val;
        if (c < 48) val = sm->accs[c*EPB+e]*SS;
        else {
            int cc = c-48, w = cc/3, i = cc-w*3;
            val = (sm->accv[cc*EPB+e] + sm->y1[i*EPB+e]*sm->t3[w*EPB+e])*SV;
        }
        atomicAdd(&g_agg[dd*AGGD+c], val);
    }
}

__global__ void k_gate() {
    int idx = blockIdx.x*blockDim.x + threadIdx.x;
    if (idx >= N_NODES*HID) return;
    int n = idx/HID, c = idx - n*HID;
    float add;
    if (c < 32) {
        float a = g_agg[n*AGGD+c];
        add = a/(1.f+expf(-a));
    } else {
        int cc = c-32, w = cc/3;
        float gg = g_agg[n*AGGD+32+w];
        add = g_agg[n*AGGD+48+cc]/(1.f+expf(-gg));
    }
    g_h[idx] = g_h[idx] + g_xself[idx] + add;
}

__global__ void k_out(const float* __restrict__ proj, float* __restrict__ out) {
    int idx = blockIdx.x*blockDim.x + threadIdx.x;
    if (idx >= N_NODES*32) return;
    int n = idx >> 5, j = idx & 31;
    float a = 0.f;
    #pragma unroll
    for (int u = 0; u < 32; ++u) a = fmaf(g_h[n*HID+u], proj[u*32+j], a);
    out[idx] = a*0.17677669529663687f;
}

extern "C" void kernel_launch(void* const* d_in, const int* in_sizes, int n_in,
                              void* d_out, int out_size) {
    const float* x      = (const float*)d_in[0];
    const float* pos    = (const float*)d_in[1];
    const int*   ei     = (const int*)  d_in[2];
    const float* embed  = (const float*)d_in[3];
    const float* proj   = (const float*)d_in[4];
    const float* lin_ws = (const float*)d_in[5];
    const float* lin_wv = (const float*)d_in[6];
    const float* sc_ws  = (const float*)d_in[7];
    const float* sc_wv  = (const float*)d_in[8];
    const float* w1     = (const float*)d_in[9];
    const float* b1     = (const float*)d_in[10];
    const float* w2     = (const float*)d_in[11];
    const float* b2     = (const float*)d_in[12];
    const float* w3     = (const float*)d_in[13];
    const float* b3     = (const float*)d_in[14];

    cudaFuncSetAttribute(k_msg, cudaFuncAttributeMaxDynamicSharedMemorySize, (int)sizeof(SmemT));

    kA<<<936, 256>>>(pos, ei, x, embed, w3, b3);
    k_radial4<<<768, 256>>>(w1, b1, w2, b2);
    for (int l = 0; l < 4; ++l) {
        k_fuse<<<64, 256>>>(l > 0 ? 1 : 0,
                            lin_ws + l*1024, lin_wv + l*256, sc_ws + l*1024, sc_wv + l*256);
        k_msg<<<384, 512, sizeof(SmemT)>>>(l, ei);
    }
    k_gate<<<640, 256>>>();
    k_out<<<256, 256>>>(proj, (float*)d_out);
}

// round 15
// speedup vs baseline: 4.6935x; 1.4745x over previous
#include <cuda_runtime.h>
#include <cuda_bf16.h>
#include <math.h>
#include <stdint.h>

#define N_NODES 2048
#define N_EDGES 49152
#define HID     80
#define AGGD    96
#define WN      3328
#define EPB     128
#define SP      132   // padded feature stride (kills epilogue bank conflicts)

__device__ float g_geo[N_EDGES * 20];
__device__ __nv_bfloat16 g_f2h[4L * N_EDGES * 64];
__device__ __nv_bfloat16 g_w3h[104L * 8192];
__device__ float g_b3r[104 * 128];
__device__ float g_h    [N_NODES * HID];
__device__ float g_hx   [N_NODES * HID];
__device__ float g_xself[N_NODES * HID];
__device__ float g_agg  [N_NODES * AGGD];

__device__ __forceinline__ unsigned s2u(const void* p) {
    unsigned a;
    asm("{ .reg .u64 t; cvta.to.shared.u64 t, %1; cvt.u32.u64 %0, t; }" : "=r"(a) : "l"(p));
    return a;
}
__device__ __forceinline__ void ldsm4(uint32_t* r, unsigned addr) {
    asm volatile("ldmatrix.sync.aligned.m8n8.x4.shared.b16 {%0,%1,%2,%3}, [%4];"
                 : "=r"(r[0]), "=r"(r[1]), "=r"(r[2]), "=r"(r[3]) : "r"(addr));
}
__device__ __forceinline__ void mma16816(float* c, const uint32_t* a, uint32_t b0, uint32_t b1) {
    asm volatile("mma.sync.aligned.m16n8k16.row.col.f32.bf16.bf16.f32 "
                 "{%0,%1,%2,%3}, {%4,%5,%6,%7}, {%8,%9}, {%0,%1,%2,%3};"
                 : "+f"(c[0]), "+f"(c[1]), "+f"(c[2]), "+f"(c[3])
                 : "r"(a[0]), "r"(a[1]), "r"(a[2]), "r"(a[3]), "r"(b0), "r"(b1));
}
__device__ __forceinline__ void cpa16(unsigned dst, const void* src) {
    asm volatile("cp.async.ca.shared.global [%0], [%1], 16;" :: "r"(dst), "l"(src) : "memory");
}
#define CPA_COMMIT() asm volatile("cp.async.commit_group;" ::: "memory")
#define CPA_WAIT0()  asm volatile("cp.async.wait_group 0;" ::: "memory")

// ---- chunk tables (26 chunks x 128 slots) ----
__device__ const int cb_[26]  = {0,0,0,0,0,0,0,0,0,0,0,0, 1536,1536,1536,1536,1536,1536,
                                 2304,2304,2304,2304, 2816,2816, 3072,3072};
__device__ const int cw_[26]  = {48,48,48,48,48,48,48,48,48,48,48,48, 48,48,48,48,48,48,
                                 16,16,16,16, 16,16, 16,16};
__device__ const int cnu_[26] = {32,32,32,32,32,32,32,32,32,32,32,32, 16,16,16,16,16,16,
                                 32,32,32,32, 16,16, 16,16};
__device__ const int cwb_[26] = {0,4,8,12,16,20,24,28,32,36,40,44, 0,8,16,24,32,40,
                                 0,4,8,12, 0,8, 0,8};
__device__ const int cbk_[26] = {0,0,0,0,0,0,0,0,0,0,0,0, 1,1,1,1,1,1, 2,2,2,2, 3,3, 4,4};

// ---------------- kA: geometry + embed-init + W3 pre-split ----------------
__global__ void kA(const float* __restrict__ pos, const int* __restrict__ ei,
                   const float* __restrict__ x, const float* __restrict__ ew,
                   const float* __restrict__ W3, const float* __restrict__ B3) {
    if (blockIdx.x < 192) {
        int e = blockIdx.x*256 + threadIdx.x;
        int s = ei[e], d = ei[N_EDGES + e];
        float rx = pos[d*3+0]-pos[s*3+0], ry = pos[d*3+1]-pos[s*3+1], rz = pos[d*3+2]-pos[s*3+2];
        float r = fmaxf(sqrtf(rx*rx+ry*ry+rz*rz), 1e-6f);
        float inv = 1.f/r;
        float dx = rx*inv, dy = ry*inv, dz = rz*inv;
        float* g = g_geo + e*20;
        const float s3 = 1.7320508075688772f;
        g[0]=s3*dx; g[1]=s3*dy; g[2]=s3*dz;
        const float c15 = 3.872983346207417f;
        float y20=c15*dx*dy, y21=c15*dy*dz, y22=1.1180339887498949f*(3.f*dz*dz-1.f);
        float y23=c15*dx*dz, y24=0.5f*c15*(dx*dx-dy*dy);
        const float s2=0.7071067811865476f, s6=0.4082482904638631f, q=0.7745966692414834f;
        g[3]=q*(-s6*y22+s2*y24); g[4]=q*(-s6*y22-s2*y24); g[5]=q*(2.f*s6*y22);
        g[6]=q*s2*y20; g[7]=q*s2*y21; g[8]=q*s2*y23;
        float u = r*(1.f/6.f);
        float u3=u*u*u, u6=u3*u3, u7=u6*u, u8=u7*u;
        float fc = (u<1.f) ? (1.f-28.f*u6+48.f*u7-21.f*u8) : 0.f;
        float pref = 0.5773502691896258f*inv*fc;
        float pir = 3.14159265358979323846f*r*(1.f/6.f);
        #pragma unroll
        for (int n = 1; n <= 8; ++n) g[8+n] = pref*sinf((float)n*pir);
    } else if (blockIdx.x < 832) {
        int idx = (blockIdx.x-192)*256 + threadIdx.x;
        if (idx >= N_NODES*HID) return;
        int n = idx/HID, c = idx - n*HID;
        float v = 0.f;
        if (c < 32) {
            float a = 0.f;
            #pragma unroll
            for (int u = 0; u < 16; ++u) a = fmaf(x[n*16+u], ew[u*32+c], a);
            v = a*0.25f;
        }
        g_h[idx] = v;
    } else {
        int b = blockIdx.x - 832;            // 0..103
        int l = b / 26, c = b - l*26;
        int base = cb_[c], W = cw_[c], nu = cnu_[c], wb = cwb_[c];
        const float* W3c = W3 + (size_t)l*64*WN;
        for (int i = threadIdx.x; i < 8192; i += 256) {
            int s = i >> 6, k = i & 63;
            int u, wo;
            if (nu == 32) { u = s & 31; wo = s >> 5; } else { u = s & 15; wo = s >> 4; }
            g_w3h[(size_t)b*8192 + i] = __float2bfloat16(W3c[(size_t)k*WN + base + u*W + wb + wo]);
        }
        if (threadIdx.x < 128) {
            int s = threadIdx.x, u, wo;
            if (nu == 32) { u = s & 31; wo = s >> 5; } else { u = s & 15; wo = s >> 4; }
            g_b3r[b*128 + s] = B3[l*WN + base + u*W + wb + wo];
        }
    }
}

// ---------------- radial MLP (all 4 layers), bf16 output ----------------
__global__ __launch_bounds__(256)
void k_radial4(const float* __restrict__ W1, const float* __restrict__ B1,
               const float* __restrict__ W2, const float* __restrict__ B2) {
    __shared__ float w1s[512], b1s[64], w2s[4096], b2s[64];
    int tid = threadIdx.x;
    int l = blockIdx.x / 192;
    int e = (blockIdx.x - l*192)*256 + tid;
    const float* W1l = W1 + l*512; const float* W2l = W2 + l*4096;
    for (int i = tid; i < 512;  i += 256) w1s[i]=W1l[i];
    for (int i = tid; i < 4096; i += 256) w2s[i]=W2l[i];
    if (tid < 64) { b1s[tid]=B1[l*64+tid]; b2s[tid]=B2[l*64+tid]; }
    __syncthreads();
    float rbf[8];
    #pragma unroll
    for (int n = 0; n < 8; ++n) rbf[n] = g_geo[e*20+9+n];
    float f1[64];
    #pragma unroll
    for (int o = 0; o < 64; ++o) {
        float a = b1s[o];
        #pragma unroll
        for (int n = 0; n < 8; ++n) a = fmaf(rbf[n], w1s[n*64+o], a);
        f1[o] = a/(1.f+__expf(-a));
    }
    size_t ob = ((size_t)l*N_EDGES + e)*64;
    for (int o = 0; o < 64; ++o) {
        float a = b2s[o];
        #pragma unroll
        for (int k = 0; k < 64; ++k) a = fmaf(f1[k], w2s[k*64+o], a);
        a = a/(1.f+__expf(-a));
        g_f2h[ob+o] = __float2bfloat16(a);
    }
}

// ---------------- fused gate(prev layer) + node linears + agg zero ----------------
__global__ __launch_bounds__(256)
void k_fuse(int do_gate, const float* __restrict__ Ws, const float* __restrict__ Wv,
            const float* __restrict__ Ss, const float* __restrict__ Sv) {
    __shared__ float ws_[1024], wv_[256], ss_[1024], sv_[256];
    int tid = threadIdx.x;
    int gid = blockIdx.x*256 + tid;
    int n = gid >> 3, slot = gid & 7;
    for (int i = tid; i < 1024; i += 256) { ws_[i]=Ws[i]; ss_[i]=Ss[i]; }
    if (tid < 256) { wv_[tid]=Wv[tid]; sv_[tid]=Sv[tid]; }
    if (do_gate) {
        #pragma unroll
        for (int cc = 0; cc < 10; ++cc) {
            int c = slot*10 + cc;
            float add;
            if (c < 32) {
                float a = g_agg[n*AGGD+c];
                add = a/(1.f+__expf(-a));
            } else {
                int c2 = c-32, w = c2/3;
                float gg = g_agg[n*AGGD+32+w];
                add = g_agg[n*AGGD+48+c2]/(1.f+__expf(-gg));
            }
            g_h[n*HID+c] = g_h[n*HID+c] + g_xself[n*HID+c] + add;
        }
    }
    __syncthreads();
    for (int i = tid; i < 32*AGGD; i += 256) g_agg[(size_t)blockIdx.x*32*AGGD + i] = 0.f;

    float hs[32], hv[48];
    #pragma unroll
    for (int i = 0; i < 32; ++i) hs[i] = g_h[n*HID+i];
    #pragma unroll
    for (int i = 0; i < 48; ++i) hv[i] = g_h[n*HID+32+i];
    const float is = 0.17677669529663687f, iv = 0.25f;
    #pragma unroll
    for (int c4 = 0; c4 < 4; ++c4) {
        int w = slot*4 + c4;
        float a=0.f, b=0.f;
        #pragma unroll
        for (int u = 0; u < 32; ++u) { a=fmaf(hs[u],ws_[u*32+w],a); b=fmaf(hs[u],ss_[u*32+w],b); }
        g_hx[n*HID+w]=a*is; g_xself[n*HID+w]=b*is;
    }
    #pragma unroll
    for (int c2 = 0; c2 < 2; ++c2) {
        int w = slot*2 + c2;
        float a0=0,a1=0,a2=0,b0=0,b1=0,b2=0;
        #pragma unroll
        for (int u = 0; u < 16; ++u) {
            float wl=wv_[u*16+w], sl=sv_[u*16+w];
            a0=fmaf(hv[u*3+0],wl,a0); a1=fmaf(hv[u*3+1],wl,a1); a2=fmaf(hv[u*3+2],wl,a2);
            b0=fmaf(hv[u*3+0],sl,b0); b1=fmaf(hv[u*3+1],sl,b1); b2=fmaf(hv[u*3+2],sl,b2);
        }
        g_hx[n*HID+32+w*3+0]=a0*iv; g_hx[n*HID+32+w*3+1]=a1*iv; g_hx[n*HID+32+w*3+2]=a2*iv;
        g_xself[n*HID+32+w*3+0]=b0*iv; g_xself[n*HID+32+w*3+1]=b1*iv; g_xself[n*HID+32+w*3+2]=b2*iv;
    }
}

// ---------------- k_msg ----------------
#define RP 72   // bf16 row pitch (144 B)

struct SmemT {
    __nv_bfloat16 Ah[128*RP];
    __nv_bfloat16 Bh[2][128*RP];
    float bias[2][128];
    float sj[32*SP];
    float p2[16*SP];
    float vj[48*SP];
    float y1[3*SP];
    float Mq[6*SP];
    float t3[16*SP];
    float accs[48*SP];
    float accv[48*SP];
    int srcs[EPB];
    int dsts[EPB];
};

__global__ __launch_bounds__(512, 1)
void k_msg(int l, const int* __restrict__ ei) {
    extern __shared__ unsigned char smraw[];
    SmemT* sm = (SmemT*)smraw;
    int tid = threadIdx.x;
    int wid = tid >> 5, lid = tid & 31;
    int e0 = blockIdx.x * EPB;
    int l26 = l * 26;

    if (tid < EPB) { sm->srcs[tid] = ei[e0+tid]; sm->dsts[tid] = ei[N_EDGES+e0+tid]; }

    // A tile via cp.async
    {
        unsigned ahU = s2u(sm->Ah);
        const char* sh = (const char*)(g_f2h + ((size_t)l*N_EDGES + e0)*64);
        for (int t = tid; t < 1024; t += 512) {
            int r = t >> 3, k8 = t & 7;
            cpa16(ahU + (unsigned)(r*144 + k8*16), sh + r*128 + k8*16);
        }
    }
    auto issueB = [&](int c) {
        unsigned bh = s2u(sm->Bh[c & 1]);
        const char* srch = (const char*)(g_w3h + (size_t)(l26 + c)*8192);
        for (int t = tid; t < 1024; t += 512) {
            int s = t >> 3, k8 = t & 7;
            cpa16(bh + (unsigned)(s*144 + k8*16), srch + s*128 + k8*16);
        }
        if (tid < 32) cpa16(s2u(&sm->bias[c & 1][0]) + tid*16,
                            (const char*)(g_b3r + (size_t)(l26 + c)*128) + tid*16);
        CPA_COMMIT();
    };
    issueB(0);
    __syncthreads();   // srcs visible

    for (int i = tid; i < EPB*80; i += 512) {
        int ee = i/80, c = i - ee*80;
        float v = g_hx[sm->srcs[ee]*HID + c];
        if (c < 32) sm->sj[c*SP+ee] = v; else sm->vj[(c-32)*SP+ee] = v;
    }
    for (int i = tid; i < EPB*9; i += 512) {
        int ee = i/9, c = i - ee*9;
        float v = g_geo[(e0+ee)*20 + c];
        if (c < 3) sm->y1[c*SP+ee] = v; else sm->Mq[(c-3)*SP+ee] = v;
    }
    __syncthreads();
    for (int i = tid; i < EPB*16; i += 512) {
        int ee = i & 127, u = i >> 7;
        float v0 = sm->vj[(u*3+0)*SP+ee], v1 = sm->vj[(u*3+1)*SP+ee], v2 = sm->vj[(u*3+2)*SP+ee];
        sm->p2[u*SP+ee] = (v0*sm->y1[ee] + v1*sm->y1[SP+ee] + v2*sm->y1[2*SP+ee])
                          * 0.5773502691896258f;
    }

    int wq = wid >> 2;
    int rgrp = (wid & 3) * 32;
    int cg = wq * 32;
    int q = lid >> 2, ln4 = lid & 3;
    unsigned ahB = s2u(sm->Ah);
    unsigned a_off = (unsigned)((rgrp + (lid & 15))*144 + ((lid >> 4)*8)*2);
    unsigned b_off = (unsigned)((cg + ((lid >> 4)*8) + (lid & 7))*144 + (((lid >> 3) & 1)*8)*2);

    uint32_t AF[4][2][4];   // A fragments, hoisted across all 26 chunks

    for (int c = 0; c < 26; ++c) {
        int wb = cwb_[c], bk = cbk_[c];
        CPA_WAIT0();
        __syncthreads();
        if (c == 0) {
            #pragma unroll
            for (int ks = 0; ks < 4; ++ks) {
                ldsm4(AF[ks][0], ahB + a_off + ks*32);
                ldsm4(AF[ks][1], ahB + a_off + 16*144 + ks*32);
            }
        }
        if (c < 25) issueB(c + 1);

        unsigned bhB = s2u(sm->Bh[c & 1]);
        const float* biasc = sm->bias[c & 1];

        float acc[2][4][4];
        #pragma unroll
        for (int i = 0; i < 2; ++i)
            #pragma unroll
            for (int j = 0; j < 4; ++j)
                #pragma unroll
                for (int k = 0; k < 4; ++k) acc[i][j][k] = 0.f;
        #pragma unroll
        for (int ks = 0; ks < 4; ++ks) {
            uint32_t Bh0[4], Bh1[4];
            ldsm4(Bh0, bhB + b_off + ks*32);
            ldsm4(Bh1, bhB + b_off + 16*144 + ks*32);
            uint32_t* Bhp[4] = {Bh0, Bh0+2, Bh1, Bh1+2};
            #pragma unroll
            for (int nt = 0; nt < 4; ++nt) {
                mma16816(acc[0][nt], AF[ks][0], Bhp[nt][0], Bhp[nt][1]);
                mma16816(acc[1][nt], AF[ks][1], Bhp[nt][0], Bhp[nt][1]);
            }
        }

        float bias8[8];
        #pragma unroll
        for (int nt = 0; nt < 4; ++nt)
            #pragma unroll
            for (int jj = 0; jj < 2; ++jj)
                bias8[nt*2+jj] = biasc[cg + nt*8 + ln4*2 + jj];

        if (bk == 0 || bk == 2) {
            #pragma unroll
            for (int i = 0; i < 4; ++i) {
                int er = rgrp + q + i*8;
                float p = 0.f;
                #pragma unroll
                for (int nt = 0; nt < 4; ++nt)
                    #pragma unroll
                    for (int jj = 0; jj < 2; ++jj) {
                        int u = nt*8 + ln4*2 + jj;
                        p = fmaf(acc[i>>1][nt][(i&1)*2+jj] + bias8[nt*2+jj],
                                 sm->sj[u*SP+er], p);
                    }
                p += __shfl_xor_sync(0xFFFFFFFFu, p, 1);
                p += __shfl_xor_sync(0xFFFFFFFFu, p, 2);
                if (ln4 == 0) {
                    if (bk == 0) sm->accs[(wb+wq)*SP+er] = p;
                    else         sm->t3[(wb+wq)*SP+er]   = p;
                }
            }
        } else if (bk == 1) {
            #pragma unroll
            for (int i = 0; i < 4; ++i) {
                int er = rgrp + q + i*8;
                #pragma unroll
                for (int h = 0; h < 2; ++h) {
                    float p = 0.f;
                    #pragma unroll
                    for (int n2 = 0; n2 < 2; ++n2) {
                        int nt = h*2 + n2;
                        #pragma unroll
                        for (int jj = 0; jj < 2; ++jj) {
                            int u = n2*8 + ln4*2 + jj;
                            p = fmaf(acc[i>>1][nt][(i&1)*2+jj] + bias8[nt*2+jj],
                                     sm->p2[u*SP+er], p);
                        }
                    }
                    p += __shfl_xor_sync(0xFFFFFFFFu, p, 1);
                    p += __shfl_xor_sync(0xFFFFFFFFu, p, 2);
                    if (ln4 == 0) sm->accs[(wb + wq*2 + h)*SP+er] += p;
                }
            }
        } else {
            #pragma unroll
            for (int i = 0; i < 4; ++i) {
                int er = rgrp + q + i*8;
                float M00=0,M11=0,M22=0,M01=0,M12=0,M02=0;
                if (bk == 4) {
                    M00=sm->Mq[er]; M11=sm->Mq[SP+er]; M22=sm->Mq[2*SP+er];
                    M01=sm->Mq[3*SP+er]; M12=sm->Mq[4*SP+er]; M02=sm->Mq[5*SP+er];
                }
                #pragma unroll
                for (int h = 0; h < 2; ++h) {
                    float a0=0.f, a1=0.f, a2=0.f;
                    #pragma unroll
                    for (int n2 = 0; n2 < 2; ++n2) {
                        int nt = h*2 + n2;
                        #pragma unroll
                        for (int jj = 0; jj < 2; ++jj) {
                            int u = n2*8 + ln4*2 + jj;
                            float bv = acc[i>>1][nt][(i&1)*2+jj] + bias8[nt*2+jj];
                            float v0 = sm->vj[(u*3+0)*SP+er];
                            float v1 = sm->vj[(u*3+1)*SP+er];
                            float v2 = sm->vj[(u*3+2)*SP+er];
                            float f0, f1, f2;
                            if (bk == 4) {
                                f0 = v0*M00 + v1*M01 + v2*M02;
                                f1 = v0*M01 + v1*M11 + v2*M12;
                                f2 = v0*M02 + v1*M12 + v2*M22;
                            } else { f0 = v0; f1 = v1; f2 = v2; }
                            a0 = fmaf(bv, f0, a0);
                            a1 = fmaf(bv, f1, a1);
                            a2 = fmaf(bv, f2, a2);
                        }
                    }
                    a0 += __shfl_xor_sync(0xFFFFFFFFu, a0, 1);
                    a0 += __shfl_xor_sync(0xFFFFFFFFu, a0, 2);
                    a1 += __shfl_xor_sync(0xFFFFFFFFu, a1, 1);
                    a1 += __shfl_xor_sync(0xFFFFFFFFu, a1, 2);
                    a2 += __shfl_xor_sync(0xFFFFFFFFu, a2, 1);
                    a2 += __shfl_xor_sync(0xFFFFFFFFu, a2, 2);
                    if (ln4 == 0) {
                        int w = wb + wq*2 + h;
                        if (bk == 3) {
                            sm->accv[(w*3+0)*SP+er] = a0;
                            sm->accv[(w*3+1)*SP+er] = a1;
                            sm->accv[(w*3+2)*SP+er] = a2;
                        } else {
                            sm->accv[(w*3+0)*SP+er] += a0;
                            sm->accv[(w*3+1)*SP+er] += a1;
                            sm->accv[(w*3+2)*SP+er] += a2;
                        }
                    }
                }
            }
        }
    }
    __syncthreads();

    const float SS = 0.029462782549439483f;  // 1/sqrt(48*24)
    const float SV = 0.025515518153991442f;  // 1/sqrt(64*24)
    int e = tid & 127, wp = tid >> 7;
    int dd = sm->dsts[e];
    for (int c = wp*24; c < wp*24+24; ++c) {
        float val;
        if (c < 48) val = sm->accs[c*SP+e]*SS;
        else {
            int cc = c-48, w = cc/3, i = cc-w*3;
            val = (sm->accv[cc*SP+e] + sm->y1[i*SP+e]*sm->t3[w*SP+e])*SV;
        }
        atomicAdd(&g_agg[dd*AGGD+c], val);
    }
}

__global__ void k_gate() {
    int idx = blockIdx.x*blockDim.x + threadIdx.x;
    if (idx >= N_NODES*HID) return;
    int n = idx/HID, c = idx - n*HID;
    float add;
    if (c < 32) {
        float a = g_agg[n*AGGD+c];
        add = a/(1.f+expf(-a));
    } else {
        int cc = c-32, w = cc/3;
        float gg = g_agg[n*AGGD+32+w];
        add = g_agg[n*AGGD+48+cc]/(1.f+expf(-gg));
    }
    g_h[idx] = g_h[idx] + g_xself[idx] + add;
}

__global__ void k_out(const float* __restrict__ proj, float* __restrict__ out) {
    int idx = blockIdx.x*blockDim.x + threadIdx.x;
    if (idx >= N_NODES*32) return;
    int n = idx >> 5, j = idx & 31;
    float a = 0.f;
    #pragma unroll
    for (int u = 0; u < 32; ++u) a = fmaf(g_h[n*HID+u], proj[u*32+j], a);
    out[idx] = a*0.17677669529663687f;
}

extern "C" void kernel_launch(void* const* d_in, const int* in_sizes, int n_in,
                              void* d_out, int out_size) {
    const float* x      = (const float*)d_in[0];
    const float* pos    = (const float*)d_in[1];
    const int*   ei     = (const int*)  d_in[2];
    const float* embed  = (const float*)d_in[3];
    const float* proj   = (const float*)d_in[4];
    const float* lin_ws = (const float*)d_in[5];
    const float* lin_wv = (const float*)d_in[6];
    const float* sc_ws  = (const float*)d_in[7];
    const float* sc_wv  = (const float*)d_in[8];
    const float* w1     = (const float*)d_in[9];
    const float* b1     = (const float*)d_in[10];
    const float* w2     = (const float*)d_in[11];
    const float* b2     = (const float*)d_in[12];
    const float* w3     = (const float*)d_in[13];
    const float* b3     = (const float*)d_in[14];

    cudaFuncSetAttribute(k_msg, cudaFuncAttributeMaxDynamicSharedMemorySize, (int)sizeof(SmemT));

    kA<<<936, 256>>>(pos, ei, x, embed, w3, b3);
    k_radial4<<<768, 256>>>(w1, b1, w2, b2);
    for (int l = 0; l < 4; ++l) {
        k_fuse<<<64, 256>>>(l > 0 ? 1 : 0,
                            lin_ws + l*1024, lin_wv + l*256, sc_ws + l*1024, sc_wv + l*256);
        k_msg<<<384, 512, sizeof(SmemT)>>>(l, ei);
    }
    k_gate<<<640, 256>>>();
    k_out<<<256, 256>>>(proj, (float*)d_out);
}